// round 8
// baseline (speedup 1.0000x reference)
#include <cuda_runtime.h>
#include <cstdint>

#define N_NODES 8192
#define F_DIM   512
#define H1_DIM  32
#define H2_DIM  16
#define E_NNZ   131072

// ---------------- scratch (static device globals; no allocs) ----------------
__device__ __align__(16) float g_xw0[N_NODES * H1_DIM];   // X @ W0
__device__ __align__(16) float g_h1 [N_NODES * H1_DIM];   // spmm(A, XW0) (pre-relu)
__device__ __align__(16) float g_ah1[N_NODES * H1_DIM];   // spmm(A, relu(h1))
__device__ __align__(16) float g_z  [N_NODES * H2_DIM];   // final latent

// ---------------- helpers -----------------------------------------------------
__device__ __forceinline__ void red_add_v4(float* p, float a, float b, float c, float d) {
    asm volatile("red.global.add.v4.f32 [%0], {%1, %2, %3, %4};"
                 :: "l"(p), "f"(a), "f"(b), "f"(c), "f"(d) : "memory");
}
__device__ __forceinline__ void fma_f32x2(unsigned long long& d,
                                          unsigned long long a,
                                          unsigned long long b) {
    asm("fma.rn.f32x2 %0, %1, %2, %0;" : "+l"(d) : "l"(a), "l"(b));
}
__device__ __forceinline__ unsigned long long pack2(float x, float y) {
    unsigned long long u;
    asm("mov.b64 %0, {%1, %2};" : "=l"(u) : "f"(x), "f"(y));
    return u;
}

// ---------------- K1: XW0 = X @ W0, smem-tiled; zeros g_h1 + g_ah1 -----------
__global__ void __launch_bounds__(256) k_xw0(const float* __restrict__ X,
                                             const float* __restrict__ W0) {
    __shared__ float sX [64 * 64];   // [row][k]
    __shared__ float sWp[32 * 64];   // [k_pair][col*2 + parity]
    int tid  = threadIdx.x;
    int wid  = tid >> 5;
    int lane = tid & 31;
    int row0 = blockIdx.x * 64;

    // pre-zero accumulators for the two spmm stages
    {
        float4 z4 = make_float4(0.f, 0.f, 0.f, 0.f);
        reinterpret_cast<float4*>(g_h1  + (size_t)row0 * 32)[tid]       = z4;
        reinterpret_cast<float4*>(g_h1  + (size_t)row0 * 32)[tid + 256] = z4;
        reinterpret_cast<float4*>(g_ah1 + (size_t)row0 * 32)[tid]       = z4;
        reinterpret_cast<float4*>(g_ah1 + (size_t)row0 * 32)[tid + 256] = z4;
    }

    unsigned long long acc[8];
#pragma unroll
    for (int r = 0; r < 8; r++) acc[r] = 0ull;

    for (int k0 = 0; k0 < F_DIM; k0 += 64) {
        __syncthreads();
#pragma unroll
        for (int q = 0; q < 4; q++) {
            int idx = q * 256 + tid;
            int r   = idx >> 4;
            int c4  = idx & 15;
            float4 v = *reinterpret_cast<const float4*>(
                &X[(size_t)(row0 + r) * F_DIM + k0 + c4 * 4]);
            *reinterpret_cast<float4*>(&sX[r * 64 + c4 * 4]) = v;
        }
#pragma unroll
        for (int q = 0; q < 2; q++) {
            int idx = q * 256 + tid;
            int kk  = idx >> 3;
            int c4  = idx & 7;
            float4 v = *reinterpret_cast<const float4*>(
                &W0[(size_t)(k0 + kk) * H1_DIM + c4 * 4]);
            int k2 = kk >> 1, par = kk & 1;
            float* b = &sWp[k2 * 64 + par];
            b[(4 * c4 + 0) * 2] = v.x;
            b[(4 * c4 + 1) * 2] = v.y;
            b[(4 * c4 + 2) * 2] = v.z;
            b[(4 * c4 + 3) * 2] = v.w;
        }
        __syncthreads();

#pragma unroll
        for (int pp = 0; pp < 16; pp++) {
            unsigned long long wa = *reinterpret_cast<const unsigned long long*>(
                &sWp[(2 * pp + 0) * 64 + 2 * lane]);
            unsigned long long wb = *reinterpret_cast<const unsigned long long*>(
                &sWp[(2 * pp + 1) * 64 + 2 * lane]);
#pragma unroll
            for (int r = 0; r < 8; r++) {
                float4 xv = *reinterpret_cast<const float4*>(
                    &sX[(wid * 8 + r) * 64 + 4 * pp]);
                fma_f32x2(acc[r], pack2(xv.x, xv.y), wa);
                fma_f32x2(acc[r], pack2(xv.z, xv.w), wb);
            }
        }
    }

#pragma unroll
    for (int r = 0; r < 8; r++) {
        unsigned long long u = acc[r];
        float lo = __int_as_float((int)(u & 0xffffffffull));
        float hi = __int_as_float((int)(u >> 32));
        g_xw0[(size_t)(row0 + wid * 8 + r) * H1_DIM + lane] = lo + hi;
    }
}

// ---------------- K2: h1 = spmm(A, XW0)  (8 threads/edge, red.v4) ----------
__global__ void k_spmm1(const int* __restrict__ rows, const int* __restrict__ cols,
                        const float* __restrict__ vals) {
    unsigned t = blockIdx.x * blockDim.x + threadIdx.x;    // < E*8
    unsigned e = t >> 3;
    unsigned s = t & 7;
    if (e >= E_NNZ) return;
    int r = rows[e];
    int c = cols[e];
    float v = vals[e];
    float4 x = *reinterpret_cast<const float4*>(&g_xw0[c * H1_DIM + s * 4]);
    red_add_v4(&g_h1[r * H1_DIM + s * 4], v * x.x, v * x.y, v * x.z, v * x.w);
}

// ---------------- K3: ah1 = spmm(A, relu(h1))  (8 threads/edge, red.v4) ----
__global__ void k_spmm2(const int* __restrict__ rows, const int* __restrict__ cols,
                        const float* __restrict__ vals) {
    unsigned t = blockIdx.x * blockDim.x + threadIdx.x;    // < E*8
    unsigned e = t >> 3;
    unsigned s = t & 7;
    if (e >= E_NNZ) return;
    int r = rows[e];
    int c = cols[e];
    float v = vals[e];
    float4 x = *reinterpret_cast<const float4*>(&g_h1[c * H1_DIM + s * 4]);
    red_add_v4(&g_ah1[r * H1_DIM + s * 4],
               v * fmaxf(x.x, 0.f), v * fmaxf(x.y, 0.f),
               v * fmaxf(x.z, 0.f), v * fmaxf(x.w, 0.f));
}

// ---------------- K4: fused heads: t = ah1@[W1|W2|W3], softmax, reparam ----
// Valid because spmm(A, h1@Wk) == (spmm(A, h1))@Wk  (associativity).
__global__ void k_fuse(const float* __restrict__ W1, const float* __restrict__ W2,
                       const float* __restrict__ W3,
                       const float* __restrict__ s1, const float* __restrict__ s2) {
    __shared__ float sW[32 * 48];
    __shared__ float srow[16 * 32];
    int tid = threadIdx.x;
    for (int i = tid; i < 32 * 16; i += 256) {
        int k = i >> 4, j = i & 15;
        sW[k * 48 + j]      = W1[i];
        sW[k * 48 + 16 + j] = W2[i];
        sW[k * 48 + 32 + j] = W3[i];
    }
    int row0 = blockIdx.x * 16;
    if (tid < 128) {
        int r  = tid >> 3;
        int c4 = (tid & 7) * 4;
        *reinterpret_cast<float4*>(&srow[r * 32 + c4]) =
            *reinterpret_cast<const float4*>(&g_ah1[(size_t)(row0 + r) * 32 + c4]);
    }
    __syncthreads();

    int rr = tid >> 4;     // local row 0..15
    int l  = tid & 15;     // output col 0..15
    float a1 = 0.f, a2 = 0.f, a3 = 0.f;
#pragma unroll
    for (int k = 0; k < 32; k++) {
        float v = srow[rr * 32 + k];
        a1 = fmaf(v, sW[k * 48 + l],      a1);
        a2 = fmaf(v, sW[k * 48 + 16 + l], a2);
        a3 = fmaf(v, sW[k * 48 + 32 + l], a3);
    }

    // softmax over the 16-lane group for a2, a3
    float m2 = a2, m3 = a3;
#pragma unroll
    for (int d = 8; d; d >>= 1) {
        m2 = fmaxf(m2, __shfl_xor_sync(0xffffffffu, m2, d));
        m3 = fmaxf(m3, __shfl_xor_sync(0xffffffffu, m3, d));
    }
    float e2 = __expf(a2 - m2), e3 = __expf(a3 - m3);
    float q2 = e2, q3 = e3;
#pragma unroll
    for (int d = 8; d; d >>= 1) {
        q2 += __shfl_xor_sync(0xffffffffu, q2, d);
        q3 += __shfl_xor_sync(0xffffffffu, q3, d);
    }
    float p2 = e2 / q2;          // z_log_en
    float p3 = e3 / q3;          // z_log_he
    int row = row0 + rr;
    float z_enn = __expf(p2) + s1[row * 16 + l] * (0.1f * __expf(p3));
    g_z[row * 16 + l] = a1 + s2[row * 16 + l] * z_enn;
}

// ---------------- K5: out = z @ z^T, FULL matrix, register->STG.128 --------
// Tile 128(i) x 64(j), thread owns rows ti+16r (r<8) and cols 4*tj..4*tj+3 —
// output per row r is one contiguous float4 -> pure STG.128 epilogue, no
// staging smem, no post-compute syncs.
// b-operand smem (szjf): k-pair-major ull layout with a 16B pad every 16 ull
// (phys word = 144*kp + 2*u + 4*(u>>4)) so the 16-lane LDS.128 read hits the
// 2-way/256B bandwidth floor.
__global__ void __launch_bounds__(256, 2) k_zzt(float* __restrict__ out) {
    __shared__ float szi [128 * 20];    // [row][16 k + pad4]
    __shared__ float szjf[8 * 144];     // [kp][padded ull cols]
    int tid = threadIdx.x;
    int i0 = blockIdx.y * 128;
    int j0 = blockIdx.x * 64;

    // i-tile: 128 rows x 16 k (float4-aligned rows, stride 20)
#pragma unroll
    for (int q = 0; q < 2; q++) {
        int idx = q * 256 + tid;
        int r = idx >> 2;
        int c = (idx & 3) * 4;
        float4 v = *reinterpret_cast<const float4*>(&g_z[(i0 + r) * 16 + c]);
        *reinterpret_cast<float4*>(&szi[r * 20 + c]) = v;
    }
    // j-tile: 64 cols, k-pair interleaved ull layout
    {
        int j = tid & 63;
        int q = tid >> 6;       // 0..3 -> k-pairs 2q, 2q+1
        float4 v = *reinterpret_cast<const float4*>(&g_z[(j0 + j) * 16 + 4 * q]);
        int w = 2 * j + 4 * (j >> 4);
        *reinterpret_cast<unsigned long long*>(&szjf[(2 * q)     * 144 + w]) = pack2(v.x, v.y);
        *reinterpret_cast<unsigned long long*>(&szjf[(2 * q + 1) * 144 + w]) = pack2(v.z, v.w);
    }
    __syncthreads();

    int ti = tid >> 4;    // 0..15 : rows ti + 16r
    int tj = tid & 15;    // 0..15 : cols 4tj..4tj+3
    int bw = 8 * tj + 4 * (tj >> 2);   // phys word of ull 4tj within a kp row

    unsigned long long acc[8][4];
#pragma unroll
    for (int r = 0; r < 8; r++)
#pragma unroll
        for (int c = 0; c < 4; c++) acc[r][c] = 0ull;

#pragma unroll
    for (int pp = 0; pp < 4; pp++) {       // two k-pairs per iteration
        float4 b0a = *reinterpret_cast<const float4*>(&szjf[(2 * pp) * 144 + bw]);
        float4 b0b = *reinterpret_cast<const float4*>(&szjf[(2 * pp) * 144 + bw + 4]);
        float4 b1a = *reinterpret_cast<const float4*>(&szjf[(2 * pp + 1) * 144 + bw]);
        float4 b1b = *reinterpret_cast<const float4*>(&szjf[(2 * pp + 1) * 144 + bw + 4]);
        unsigned long long b0[4] = { pack2(b0a.x, b0a.y), pack2(b0a.z, b0a.w),
                                     pack2(b0b.x, b0b.y), pack2(b0b.z, b0b.w) };
        unsigned long long b1[4] = { pack2(b1a.x, b1a.y), pack2(b1a.z, b1a.w),
                                     pack2(b1b.x, b1b.y), pack2(b1b.z, b1b.w) };
#pragma unroll
        for (int r = 0; r < 8; r++) {
            float4 a4 = *reinterpret_cast<const float4*>(
                &szi[(ti + 16 * r) * 20 + 4 * pp]);      // broadcast (2 addrs/warp)
            unsigned long long xa = pack2(a4.x, a4.y);   // k-pair 2pp
            unsigned long long xb = pack2(a4.z, a4.w);   // k-pair 2pp+1
#pragma unroll
            for (int c = 0; c < 4; c++) {
                fma_f32x2(acc[r][c], xa, b0[c]);
                fma_f32x2(acc[r][c], xb, b1[c]);
            }
        }
    }

    // epilogue: one STG.128 per row, straight from registers
#pragma unroll
    for (int r = 0; r < 8; r++) {
        float4 o;
        {
            unsigned long long u = acc[r][0];
            o.x = __int_as_float((int)(u & 0xffffffffull)) + __int_as_float((int)(u >> 32));
            u = acc[r][1];
            o.y = __int_as_float((int)(u & 0xffffffffull)) + __int_as_float((int)(u >> 32));
            u = acc[r][2];
            o.z = __int_as_float((int)(u & 0xffffffffull)) + __int_as_float((int)(u >> 32));
            u = acc[r][3];
            o.w = __int_as_float((int)(u & 0xffffffffull)) + __int_as_float((int)(u >> 32));
        }
        *reinterpret_cast<float4*>(
            &out[(size_t)(i0 + ti + 16 * r) * N_NODES + j0 + 4 * tj]) = o;
    }
}

// ---------------- launcher ---------------------------------------------------
extern "C" void kernel_launch(void* const* d_in, const int* in_sizes, int n_in,
                              void* d_out, int out_size) {
    const float* features = (const float*)d_in[0];
    const int*   adj_rows = (const int*)  d_in[1];
    const int*   adj_cols = (const int*)  d_in[2];
    const float* adj_val  = (const float*)d_in[3];
    const float* W0       = (const float*)d_in[4];
    const float* W1       = (const float*)d_in[5];
    const float* W2       = (const float*)d_in[6];
    const float* W3       = (const float*)d_in[7];
    const float* sample_1 = (const float*)d_in[8];
    const float* sample_2 = (const float*)d_in[9];
    float* out = (float*)d_out;

    k_xw0  <<<N_NODES / 64, 256>>>(features, W0);
    k_spmm1<<<E_NNZ * 8 / 256, 256>>>(adj_rows, adj_cols, adj_val);
    k_spmm2<<<E_NNZ * 8 / 256, 256>>>(adj_rows, adj_cols, adj_val);
    k_fuse <<<N_NODES / 16, 256>>>(W1, W2, W3, sample_1, sample_2);

    dim3 zgrid(N_NODES / 64, N_NODES / 128);   // 128 x 64 = 8192 blocks
    k_zzt<<<zgrid, 256>>>(out);
}

// round 9
// speedup vs baseline: 1.0978x; 1.0978x over previous
#include <cuda_runtime.h>
#include <cstdint>

#define N_NODES 8192
#define F_DIM   512
#define H1_DIM  32
#define H2_DIM  16
#define E_NNZ   131072

// ---------------- scratch (static device globals; no allocs) ----------------
__device__ __align__(16) float g_xw0[N_NODES * H1_DIM];   // X @ W0
__device__ __align__(16) float g_h1 [N_NODES * H1_DIM];   // spmm(A, XW0) (pre-relu)
__device__ __align__(16) float g_ah1[N_NODES * H1_DIM];   // spmm(A, relu(h1))
__device__ __align__(16) float g_z  [N_NODES * H2_DIM];   // final latent

// ---------------- helpers -----------------------------------------------------
__device__ __forceinline__ void red_add_v4(float* p, float a, float b, float c, float d) {
    asm volatile("red.global.add.v4.f32 [%0], {%1, %2, %3, %4};"
                 :: "l"(p), "f"(a), "f"(b), "f"(c), "f"(d) : "memory");
}
__device__ __forceinline__ void fma_f32x2(unsigned long long& d,
                                          unsigned long long a,
                                          unsigned long long b) {
    asm("fma.rn.f32x2 %0, %1, %2, %0;" : "+l"(d) : "l"(a), "l"(b));
}
__device__ __forceinline__ unsigned long long pack2(float x, float y) {
    unsigned long long u;
    asm("mov.b64 %0, {%1, %2};" : "=l"(u) : "f"(x), "f"(y));
    return u;
}

// ---------------- K1: XW0 = X @ W0, smem-tiled; zeros g_h1 + g_ah1 -----------
__global__ void __launch_bounds__(256) k_xw0(const float* __restrict__ X,
                                             const float* __restrict__ W0) {
    __shared__ float sX [64 * 64];   // [row][k]
    __shared__ float sWp[32 * 64];   // [k_pair][col*2 + parity]
    int tid  = threadIdx.x;
    int wid  = tid >> 5;
    int lane = tid & 31;
    int row0 = blockIdx.x * 64;

    // pre-zero accumulators for the two spmm stages
    {
        float4 z4 = make_float4(0.f, 0.f, 0.f, 0.f);
        reinterpret_cast<float4*>(g_h1  + (size_t)row0 * 32)[tid]       = z4;
        reinterpret_cast<float4*>(g_h1  + (size_t)row0 * 32)[tid + 256] = z4;
        reinterpret_cast<float4*>(g_ah1 + (size_t)row0 * 32)[tid]       = z4;
        reinterpret_cast<float4*>(g_ah1 + (size_t)row0 * 32)[tid + 256] = z4;
    }

    unsigned long long acc[8];
#pragma unroll
    for (int r = 0; r < 8; r++) acc[r] = 0ull;

    for (int k0 = 0; k0 < F_DIM; k0 += 64) {
        __syncthreads();
#pragma unroll
        for (int q = 0; q < 4; q++) {
            int idx = q * 256 + tid;
            int r   = idx >> 4;
            int c4  = idx & 15;
            float4 v = *reinterpret_cast<const float4*>(
                &X[(size_t)(row0 + r) * F_DIM + k0 + c4 * 4]);
            *reinterpret_cast<float4*>(&sX[r * 64 + c4 * 4]) = v;
        }
#pragma unroll
        for (int q = 0; q < 2; q++) {
            int idx = q * 256 + tid;
            int kk  = idx >> 3;
            int c4  = idx & 7;
            float4 v = *reinterpret_cast<const float4*>(
                &W0[(size_t)(k0 + kk) * H1_DIM + c4 * 4]);
            int k2 = kk >> 1, par = kk & 1;
            float* b = &sWp[k2 * 64 + par];
            b[(4 * c4 + 0) * 2] = v.x;
            b[(4 * c4 + 1) * 2] = v.y;
            b[(4 * c4 + 2) * 2] = v.z;
            b[(4 * c4 + 3) * 2] = v.w;
        }
        __syncthreads();

#pragma unroll
        for (int pp = 0; pp < 16; pp++) {
            unsigned long long wa = *reinterpret_cast<const unsigned long long*>(
                &sWp[(2 * pp + 0) * 64 + 2 * lane]);
            unsigned long long wb = *reinterpret_cast<const unsigned long long*>(
                &sWp[(2 * pp + 1) * 64 + 2 * lane]);
#pragma unroll
            for (int r = 0; r < 8; r++) {
                float4 xv = *reinterpret_cast<const float4*>(
                    &sX[(wid * 8 + r) * 64 + 4 * pp]);
                fma_f32x2(acc[r], pack2(xv.x, xv.y), wa);
                fma_f32x2(acc[r], pack2(xv.z, xv.w), wb);
            }
        }
    }

#pragma unroll
    for (int r = 0; r < 8; r++) {
        unsigned long long u = acc[r];
        float lo = __int_as_float((int)(u & 0xffffffffull));
        float hi = __int_as_float((int)(u >> 32));
        g_xw0[(size_t)(row0 + wid * 8 + r) * H1_DIM + lane] = lo + hi;
    }
}

// ---------------- K2: h1 = spmm(A, XW0)  (8 threads/edge, red.v4) ----------
__global__ void k_spmm1(const int* __restrict__ rows, const int* __restrict__ cols,
                        const float* __restrict__ vals) {
    unsigned t = blockIdx.x * blockDim.x + threadIdx.x;    // < E*8
    unsigned e = t >> 3;
    unsigned s = t & 7;
    if (e >= E_NNZ) return;
    int r = rows[e];
    int c = cols[e];
    float v = vals[e];
    float4 x = *reinterpret_cast<const float4*>(&g_xw0[c * H1_DIM + s * 4]);
    red_add_v4(&g_h1[r * H1_DIM + s * 4], v * x.x, v * x.y, v * x.z, v * x.w);
}

// ---------------- K3: ah1 = spmm(A, relu(h1))  (8 threads/edge, red.v4) ----
__global__ void k_spmm2(const int* __restrict__ rows, const int* __restrict__ cols,
                        const float* __restrict__ vals) {
    unsigned t = blockIdx.x * blockDim.x + threadIdx.x;    // < E*8
    unsigned e = t >> 3;
    unsigned s = t & 7;
    if (e >= E_NNZ) return;
    int r = rows[e];
    int c = cols[e];
    float v = vals[e];
    float4 x = *reinterpret_cast<const float4*>(&g_h1[c * H1_DIM + s * 4]);
    red_add_v4(&g_ah1[r * H1_DIM + s * 4],
               v * fmaxf(x.x, 0.f), v * fmaxf(x.y, 0.f),
               v * fmaxf(x.z, 0.f), v * fmaxf(x.w, 0.f));
}

// ---------------- K4: fused heads: t = ah1@[W1|W2|W3], softmax, reparam ----
// Valid because spmm(A, h1@Wk) == (spmm(A, h1))@Wk  (associativity).
// 256 blocks x 32 rows; all 256 threads participate in smem loads; two
// register-resident passes, no inter-pass syncs (srow is read-only after sync).
__global__ void __launch_bounds__(256) k_fuse(
        const float* __restrict__ W1, const float* __restrict__ W2,
        const float* __restrict__ W3,
        const float* __restrict__ s1, const float* __restrict__ s2) {
    __shared__ float sW[32 * 48];
    __shared__ float srow[32 * 32];
    int tid = threadIdx.x;
    // weights: 512 elems per matrix; 2 elems/thread each
    for (int i = tid; i < 32 * 16; i += 256) {
        int k = i >> 4, j = i & 15;
        sW[k * 48 + j]      = W1[i];
        sW[k * 48 + 16 + j] = W2[i];
        sW[k * 48 + 32 + j] = W3[i];
    }
    int row0 = blockIdx.x * 32;
    // 32 rows x 32 floats = 256 float4, 1/thread
    {
        int r  = tid >> 3;
        int c4 = (tid & 7) * 4;
        *reinterpret_cast<float4*>(&srow[r * 32 + c4]) =
            *reinterpret_cast<const float4*>(&g_ah1[(size_t)(row0 + r) * 32 + c4]);
    }
    __syncthreads();

    int l = tid & 15;      // output col 0..15
#pragma unroll
    for (int pass = 0; pass < 2; pass++) {
        int rr = pass * 16 + (tid >> 4);    // local row
        float a1 = 0.f, a2 = 0.f, a3 = 0.f;
#pragma unroll
        for (int k = 0; k < 32; k++) {
            float v = srow[rr * 32 + k];
            a1 = fmaf(v, sW[k * 48 + l],      a1);
            a2 = fmaf(v, sW[k * 48 + 16 + l], a2);
            a3 = fmaf(v, sW[k * 48 + 32 + l], a3);
        }
        // softmax over the 16-lane group for a2, a3
        float m2 = a2, m3 = a3;
#pragma unroll
        for (int d = 8; d; d >>= 1) {
            m2 = fmaxf(m2, __shfl_xor_sync(0xffffffffu, m2, d));
            m3 = fmaxf(m3, __shfl_xor_sync(0xffffffffu, m3, d));
        }
        float e2 = __expf(a2 - m2), e3 = __expf(a3 - m3);
        float q2 = e2, q3 = e3;
#pragma unroll
        for (int d = 8; d; d >>= 1) {
            q2 += __shfl_xor_sync(0xffffffffu, q2, d);
            q3 += __shfl_xor_sync(0xffffffffu, q3, d);
        }
        float p2 = e2 / q2;          // z_log_en
        float p3 = e3 / q3;          // z_log_he
        int row = row0 + rr;
        float z_enn = __expf(p2) + s1[row * 16 + l] * (0.1f * __expf(p3));
        g_z[row * 16 + l] = a1 + s2[row * 16 + l] * z_enn;
    }
}

// ---------------- K6: out = z @ z^T, 128x64 tiles, occ=2 (R7 proven) -------
// Direct tile: stored straight from registers (coalesced 64B half-warp STG.32,
// zero smem traffic, no extra syncs). Mirror tile: staged in sm_m[64][132]
// (odd-vec stride: <=2-way STS, conflict-free LDS.128), 512B STG.128 streams.
#define ZPAD   18
#define SM_STR 132    // 33 vecs
#define ZZT_SMEM_BYTES (64 * SM_STR * 4)   // 33792; compute phase needs 13824

__global__ void __launch_bounds__(256, 2) k_zzt(float* __restrict__ out) {
    extern __shared__ float sm[];
    float* szi  = sm;                       // [128][ZPAD] (compute phase)
    float* szj  = sm + 128 * ZPAD;          // [64][ZPAD]
    float* sm_m = sm;                       // [64][SM_STR] (staging, overlaps)

    // block -> (lower-tri square tile l, half h)
    int bx = blockIdx.x;
    int l  = bx >> 1;
    int h  = bx & 1;
    float f = sqrtf(8.0f * (float)l + 1.0f);
    int bi = (int)((f - 1.0f) * 0.5f);
    while ((bi + 1) * (bi + 2) / 2 <= l) bi++;
    while (bi * (bi + 1) / 2 > l) bi--;
    int bj = l - bi * (bi + 1) / 2;

    int i0 = bi * 128;
    int j0 = bj * 128 + h * 64;
    int tid = threadIdx.x;

    // load z tiles
#pragma unroll
    for (int q = 0; q < 2; q++) {
        int idx = q * 256 + tid;
        int r = idx >> 2;
        int c = (idx & 3) * 4;
        float4 vi = *reinterpret_cast<const float4*>(&g_z[(i0 + r) * 16 + c]);
        *reinterpret_cast<float2*>(&szi[r * ZPAD + c])     = make_float2(vi.x, vi.y);
        *reinterpret_cast<float2*>(&szi[r * ZPAD + c + 2]) = make_float2(vi.z, vi.w);
    }
    {
        int r = tid >> 2;
        int c = (tid & 3) * 4;
        float4 vj = *reinterpret_cast<const float4*>(&g_z[(j0 + r) * 16 + c]);
        *reinterpret_cast<float2*>(&szj[r * ZPAD + c])     = make_float2(vj.x, vj.y);
        *reinterpret_cast<float2*>(&szj[r * ZPAD + c + 2]) = make_float2(vj.z, vj.w);
    }
    __syncthreads();

    int ti = tid >> 4;    // 0..15 : rows ti+16r
    int tj = tid & 15;    // 0..15 : cols tj+16c (c<4)

    unsigned long long acc[8][4];
#pragma unroll
    for (int r = 0; r < 8; r++)
#pragma unroll
        for (int c = 0; c < 4; c++) acc[r][c] = 0ull;

#pragma unroll
    for (int kp = 0; kp < 8; kp++) {
        unsigned long long a[8], b[4];
#pragma unroll
        for (int r = 0; r < 8; r++)
            a[r] = *reinterpret_cast<const unsigned long long*>(
                &szi[(ti + 16 * r) * ZPAD + 2 * kp]);
#pragma unroll
        for (int c = 0; c < 4; c++)
            b[c] = *reinterpret_cast<const unsigned long long*>(
                &szj[(tj + 16 * c) * ZPAD + 2 * kp]);
#pragma unroll
        for (int r = 0; r < 8; r++)
#pragma unroll
            for (int c = 0; c < 4; c++) fma_f32x2(acc[r][c], a[r], b[c]);
    }

    bool mirror = (bi != bj);

    // finalize values; store direct tile straight from registers
    float res[8][4];
#pragma unroll
    for (int r = 0; r < 8; r++)
#pragma unroll
        for (int c = 0; c < 4; c++) {
            unsigned long long u = acc[r][c];
            float lo = __int_as_float((int)(u & 0xffffffffull));
            float hi = __int_as_float((int)(u >> 32));
            res[r][c] = lo + hi;
            out[(size_t)(i0 + ti + 16 * r) * N_NODES + j0 + tj + 16 * c] = res[r][c];
        }

    // mirror tile via smem transpose staging
    if (mirror) {
        __syncthreads();    // compute-phase smem reads done before overwrite
#pragma unroll
        for (int r = 0; r < 8; r++)
#pragma unroll
            for (int c = 0; c < 4; c++)
                sm_m[(tj + 16 * c) * SM_STR + ti + 16 * r] = res[r][c];
        __syncthreads();

        int lane = tid & 31;
        int w    = tid >> 5;   // 0..7
#pragma unroll
        for (int m = 0; m < 8; m++) {
            int j = 8 * w + m;
            float4 v = *reinterpret_cast<const float4*>(&sm_m[j * SM_STR + 4 * lane]);
            *reinterpret_cast<float4*>(
                &out[(size_t)(j0 + j) * N_NODES + i0 + 4 * lane]) = v;
        }
    }
}

// ---------------- launcher ---------------------------------------------------
extern "C" void kernel_launch(void* const* d_in, const int* in_sizes, int n_in,
                              void* d_out, int out_size) {
    const float* features = (const float*)d_in[0];
    const int*   adj_rows = (const int*)  d_in[1];
    const int*   adj_cols = (const int*)  d_in[2];
    const float* adj_val  = (const float*)d_in[3];
    const float* W0       = (const float*)d_in[4];
    const float* W1       = (const float*)d_in[5];
    const float* W2       = (const float*)d_in[6];
    const float* W3       = (const float*)d_in[7];
    const float* sample_1 = (const float*)d_in[8];
    const float* sample_2 = (const float*)d_in[9];
    float* out = (float*)d_out;

    cudaFuncSetAttribute(k_zzt, cudaFuncAttributeMaxDynamicSharedMemorySize,
                         ZZT_SMEM_BYTES);

    k_xw0  <<<N_NODES / 64, 256>>>(features, W0);
    k_spmm1<<<E_NNZ * 8 / 256, 256>>>(adj_rows, adj_cols, adj_val);
    k_spmm2<<<E_NNZ * 8 / 256, 256>>>(adj_rows, adj_cols, adj_val);
    k_fuse <<<N_NODES / 32, 256>>>(W1, W2, W3, sample_1, sample_2);

    int ntiles = (N_NODES / 128) * (N_NODES / 128 + 1) / 2;   // 2080
    k_zzt<<<ntiles * 2, 256, ZZT_SMEM_BYTES>>>(out);
}

// round 10
// speedup vs baseline: 1.1858x; 1.0801x over previous
#include <cuda_runtime.h>
#include <cstdint>

#define N_NODES 8192
#define F_DIM   512
#define H1_DIM  32
#define H2_DIM  16
#define E_NNZ   131072

// ---------------- scratch (static device globals; no allocs) ----------------
__device__ __align__(16) float g_xw0[N_NODES * H1_DIM];   // X @ W0
__device__ __align__(16) float g_h1 [N_NODES * H1_DIM];   // spmm(A, XW0) (pre-relu)
__device__ __align__(16) float g_ah1[N_NODES * H1_DIM];   // spmm(A, relu(h1))
__device__ __align__(16) float g_z  [N_NODES * H2_DIM];   // final latent

// ---------------- helpers -----------------------------------------------------
__device__ __forceinline__ void red_add_v4(float* p, float a, float b, float c, float d) {
    asm volatile("red.global.add.v4.f32 [%0], {%1, %2, %3, %4};"
                 :: "l"(p), "f"(a), "f"(b), "f"(c), "f"(d) : "memory");
}
__device__ __forceinline__ void fma_f32x2(unsigned long long& d,
                                          unsigned long long a,
                                          unsigned long long b) {
    asm("fma.rn.f32x2 %0, %1, %2, %0;" : "+l"(d) : "l"(a), "l"(b));
}
__device__ __forceinline__ unsigned long long pack2(float x, float y) {
    unsigned long long u;
    asm("mov.b64 %0, {%1, %2};" : "=l"(u) : "f"(x), "f"(y));
    return u;
}

// ---------------- K1: XW0 = X @ W0, smem-tiled; zeros g_h1 + g_ah1 -----------
__global__ void __launch_bounds__(256) k_xw0(const float* __restrict__ X,
                                             const float* __restrict__ W0) {
    __shared__ float sX [64 * 64];   // [row][k]
    __shared__ float sWp[32 * 64];   // [k_pair][col*2 + parity]
    int tid  = threadIdx.x;
    int wid  = tid >> 5;
    int lane = tid & 31;
    int row0 = blockIdx.x * 64;

    // pre-zero accumulators for the two spmm stages
    {
        float4 z4 = make_float4(0.f, 0.f, 0.f, 0.f);
        reinterpret_cast<float4*>(g_h1  + (size_t)row0 * 32)[tid]       = z4;
        reinterpret_cast<float4*>(g_h1  + (size_t)row0 * 32)[tid + 256] = z4;
        reinterpret_cast<float4*>(g_ah1 + (size_t)row0 * 32)[tid]       = z4;
        reinterpret_cast<float4*>(g_ah1 + (size_t)row0 * 32)[tid + 256] = z4;
    }

    unsigned long long acc[8];
#pragma unroll
    for (int r = 0; r < 8; r++) acc[r] = 0ull;

    for (int k0 = 0; k0 < F_DIM; k0 += 64) {
        __syncthreads();
#pragma unroll
        for (int q = 0; q < 4; q++) {
            int idx = q * 256 + tid;
            int r   = idx >> 4;
            int c4  = idx & 15;
            float4 v = *reinterpret_cast<const float4*>(
                &X[(size_t)(row0 + r) * F_DIM + k0 + c4 * 4]);
            *reinterpret_cast<float4*>(&sX[r * 64 + c4 * 4]) = v;
        }
#pragma unroll
        for (int q = 0; q < 2; q++) {
            int idx = q * 256 + tid;
            int kk  = idx >> 3;
            int c4  = idx & 7;
            float4 v = *reinterpret_cast<const float4*>(
                &W0[(size_t)(k0 + kk) * H1_DIM + c4 * 4]);
            int k2 = kk >> 1, par = kk & 1;
            float* b = &sWp[k2 * 64 + par];
            b[(4 * c4 + 0) * 2] = v.x;
            b[(4 * c4 + 1) * 2] = v.y;
            b[(4 * c4 + 2) * 2] = v.z;
            b[(4 * c4 + 3) * 2] = v.w;
        }
        __syncthreads();

#pragma unroll
        for (int pp = 0; pp < 16; pp++) {
            unsigned long long wa = *reinterpret_cast<const unsigned long long*>(
                &sWp[(2 * pp + 0) * 64 + 2 * lane]);
            unsigned long long wb = *reinterpret_cast<const unsigned long long*>(
                &sWp[(2 * pp + 1) * 64 + 2 * lane]);
#pragma unroll
            for (int r = 0; r < 8; r++) {
                float4 xv = *reinterpret_cast<const float4*>(
                    &sX[(wid * 8 + r) * 64 + 4 * pp]);
                fma_f32x2(acc[r], pack2(xv.x, xv.y), wa);
                fma_f32x2(acc[r], pack2(xv.z, xv.w), wb);
            }
        }
    }

#pragma unroll
    for (int r = 0; r < 8; r++) {
        unsigned long long u = acc[r];
        float lo = __int_as_float((int)(u & 0xffffffffull));
        float hi = __int_as_float((int)(u >> 32));
        g_xw0[(size_t)(row0 + wid * 8 + r) * H1_DIM + lane] = lo + hi;
    }
}

// ---------------- K2: h1 = spmm(A, XW0)  (8 threads/edge, red.v4) ----------
__global__ void k_spmm1(const int* __restrict__ rows, const int* __restrict__ cols,
                        const float* __restrict__ vals) {
    unsigned t = blockIdx.x * blockDim.x + threadIdx.x;    // < E*8
    unsigned e = t >> 3;
    unsigned s = t & 7;
    if (e >= E_NNZ) return;
    int r = rows[e];
    int c = cols[e];
    float v = vals[e];
    float4 x = *reinterpret_cast<const float4*>(&g_xw0[c * H1_DIM + s * 4]);
    red_add_v4(&g_h1[r * H1_DIM + s * 4], v * x.x, v * x.y, v * x.z, v * x.w);
}

// ---------------- K3: ah1 = spmm(A, relu(h1))  (8 threads/edge, red.v4) ----
__global__ void k_spmm2(const int* __restrict__ rows, const int* __restrict__ cols,
                        const float* __restrict__ vals) {
    unsigned t = blockIdx.x * blockDim.x + threadIdx.x;    // < E*8
    unsigned e = t >> 3;
    unsigned s = t & 7;
    if (e >= E_NNZ) return;
    int r = rows[e];
    int c = cols[e];
    float v = vals[e];
    float4 x = *reinterpret_cast<const float4*>(&g_h1[c * H1_DIM + s * 4]);
    red_add_v4(&g_ah1[r * H1_DIM + s * 4],
               v * fmaxf(x.x, 0.f), v * fmaxf(x.y, 0.f),
               v * fmaxf(x.z, 0.f), v * fmaxf(x.w, 0.f));
}

// ---------------- K4: fused heads: t = ah1@[W1|W2|W3], softmax, reparam ----
// Valid because spmm(A, h1@Wk) == (spmm(A, h1))@Wk  (associativity).
// R8-measured form: grid 512 x 16 rows, single pass, lean registers.
__global__ void __launch_bounds__(256) k_fuse(
        const float* __restrict__ W1, const float* __restrict__ W2,
        const float* __restrict__ W3,
        const float* __restrict__ s1, const float* __restrict__ s2) {
    __shared__ float sW[32 * 48];
    __shared__ float srow[16 * 32];
    int tid = threadIdx.x;
    for (int i = tid; i < 32 * 16; i += 256) {
        int k = i >> 4, j = i & 15;
        sW[k * 48 + j]      = W1[i];
        sW[k * 48 + 16 + j] = W2[i];
        sW[k * 48 + 32 + j] = W3[i];
    }
    int row0 = blockIdx.x * 16;
    if (tid < 128) {
        int r  = tid >> 3;
        int c4 = (tid & 7) * 4;
        *reinterpret_cast<float4*>(&srow[r * 32 + c4]) =
            *reinterpret_cast<const float4*>(&g_ah1[(size_t)(row0 + r) * 32 + c4]);
    }
    __syncthreads();

    int rr = tid >> 4;     // local row 0..15
    int l  = tid & 15;     // output col 0..15
    float a1 = 0.f, a2 = 0.f, a3 = 0.f;
#pragma unroll
    for (int k = 0; k < 32; k++) {
        float v = srow[rr * 32 + k];
        a1 = fmaf(v, sW[k * 48 + l],      a1);
        a2 = fmaf(v, sW[k * 48 + 16 + l], a2);
        a3 = fmaf(v, sW[k * 48 + 32 + l], a3);
    }

    float m2 = a2, m3 = a3;
#pragma unroll
    for (int d = 8; d; d >>= 1) {
        m2 = fmaxf(m2, __shfl_xor_sync(0xffffffffu, m2, d));
        m3 = fmaxf(m3, __shfl_xor_sync(0xffffffffu, m3, d));
    }
    float e2 = __expf(a2 - m2), e3 = __expf(a3 - m3);
    float q2 = e2, q3 = e3;
#pragma unroll
    for (int d = 8; d; d >>= 1) {
        q2 += __shfl_xor_sync(0xffffffffu, q2, d);
        q3 += __shfl_xor_sync(0xffffffffu, q3, d);
    }
    float p2 = e2 / q2;          // z_log_en
    float p3 = e3 / q3;          // z_log_he
    int row = row0 + rr;
    float z_enn = __expf(p2) + s1[row * 16 + l] * (0.1f * __expf(p3));
    g_z[row * 16 + l] = a1 + s2[row * 16 + l] * z_enn;
}

// ---------------- K6: out = z @ z^T, 128x64 tiles, occ=2 (R7 proven) -------
// Output stores use __stcs (evict-first streaming hint): the 256MB output is
// 2x L2 capacity, caching it is pure pollution.
#define ZPAD   18
#define SM_STR 132    // 33 vecs
#define ZZT_SMEM_BYTES (64 * SM_STR * 4)   // 33792; compute phase needs 13824

__global__ void __launch_bounds__(256, 2) k_zzt(float* __restrict__ out) {
    extern __shared__ float sm[];
    float* szi  = sm;                       // [128][ZPAD] (compute phase)
    float* szj  = sm + 128 * ZPAD;          // [64][ZPAD]
    float* sm_m = sm;                       // [64][SM_STR] (staging, overlaps)

    // block -> (lower-tri square tile l, half h)
    int bx = blockIdx.x;
    int l  = bx >> 1;
    int h  = bx & 1;
    float f = sqrtf(8.0f * (float)l + 1.0f);
    int bi = (int)((f - 1.0f) * 0.5f);
    while ((bi + 1) * (bi + 2) / 2 <= l) bi++;
    while (bi * (bi + 1) / 2 > l) bi--;
    int bj = l - bi * (bi + 1) / 2;

    int i0 = bi * 128;
    int j0 = bj * 128 + h * 64;
    int tid = threadIdx.x;

    // load z tiles
#pragma unroll
    for (int q = 0; q < 2; q++) {
        int idx = q * 256 + tid;
        int r = idx >> 2;
        int c = (idx & 3) * 4;
        float4 vi = *reinterpret_cast<const float4*>(&g_z[(i0 + r) * 16 + c]);
        *reinterpret_cast<float2*>(&szi[r * ZPAD + c])     = make_float2(vi.x, vi.y);
        *reinterpret_cast<float2*>(&szi[r * ZPAD + c + 2]) = make_float2(vi.z, vi.w);
    }
    {
        int r = tid >> 2;
        int c = (tid & 3) * 4;
        float4 vj = *reinterpret_cast<const float4*>(&g_z[(j0 + r) * 16 + c]);
        *reinterpret_cast<float2*>(&szj[r * ZPAD + c])     = make_float2(vj.x, vj.y);
        *reinterpret_cast<float2*>(&szj[r * ZPAD + c + 2]) = make_float2(vj.z, vj.w);
    }
    __syncthreads();

    int ti = tid >> 4;    // 0..15 : rows ti+16r
    int tj = tid & 15;    // 0..15 : cols tj+16c (c<4)

    unsigned long long acc[8][4];
#pragma unroll
    for (int r = 0; r < 8; r++)
#pragma unroll
        for (int c = 0; c < 4; c++) acc[r][c] = 0ull;

#pragma unroll
    for (int kp = 0; kp < 8; kp++) {
        unsigned long long a[8], b[4];
#pragma unroll
        for (int r = 0; r < 8; r++)
            a[r] = *reinterpret_cast<const unsigned long long*>(
                &szi[(ti + 16 * r) * ZPAD + 2 * kp]);
#pragma unroll
        for (int c = 0; c < 4; c++)
            b[c] = *reinterpret_cast<const unsigned long long*>(
                &szj[(tj + 16 * c) * ZPAD + 2 * kp]);
#pragma unroll
        for (int r = 0; r < 8; r++)
#pragma unroll
            for (int c = 0; c < 4; c++) fma_f32x2(acc[r][c], a[r], b[c]);
    }

    bool mirror = (bi != bj);

    // finalize values; store direct tile straight from registers (streaming)
    float res[8][4];
#pragma unroll
    for (int r = 0; r < 8; r++)
#pragma unroll
        for (int c = 0; c < 4; c++) {
            unsigned long long u = acc[r][c];
            float lo = __int_as_float((int)(u & 0xffffffffull));
            float hi = __int_as_float((int)(u >> 32));
            res[r][c] = lo + hi;
            __stcs(&out[(size_t)(i0 + ti + 16 * r) * N_NODES + j0 + tj + 16 * c],
                   res[r][c]);
        }

    // mirror tile via smem transpose staging
    if (mirror) {
        __syncthreads();    // compute-phase smem reads done before overwrite
#pragma unroll
        for (int r = 0; r < 8; r++)
#pragma unroll
            for (int c = 0; c < 4; c++)
                sm_m[(tj + 16 * c) * SM_STR + ti + 16 * r] = res[r][c];
        __syncthreads();

        int lane = tid & 31;
        int w    = tid >> 5;   // 0..7
#pragma unroll
        for (int m = 0; m < 8; m++) {
            int j = 8 * w + m;
            float4 v = *reinterpret_cast<const float4*>(&sm_m[j * SM_STR + 4 * lane]);
            __stcs(reinterpret_cast<float4*>(
                       &out[(size_t)(j0 + j) * N_NODES + i0 + 4 * lane]), v);
        }
    }
}

// ---------------- launcher ---------------------------------------------------
extern "C" void kernel_launch(void* const* d_in, const int* in_sizes, int n_in,
                              void* d_out, int out_size) {
    const float* features = (const float*)d_in[0];
    const int*   adj_rows = (const int*)  d_in[1];
    const int*   adj_cols = (const int*)  d_in[2];
    const float* adj_val  = (const float*)d_in[3];
    const float* W0       = (const float*)d_in[4];
    const float* W1       = (const float*)d_in[5];
    const float* W2       = (const float*)d_in[6];
    const float* W3       = (const float*)d_in[7];
    const float* sample_1 = (const float*)d_in[8];
    const float* sample_2 = (const float*)d_in[9];
    float* out = (float*)d_out;

    cudaFuncSetAttribute(k_zzt, cudaFuncAttributeMaxDynamicSharedMemorySize,
                         ZZT_SMEM_BYTES);

    k_xw0  <<<N_NODES / 64, 256>>>(features, W0);
    k_spmm1<<<E_NNZ * 8 / 256, 256>>>(adj_rows, adj_cols, adj_val);
    k_spmm2<<<E_NNZ * 8 / 256, 256>>>(adj_rows, adj_cols, adj_val);
    k_fuse <<<N_NODES / 16, 256>>>(W1, W2, W3, sample_1, sample_2);

    int ntiles = (N_NODES / 128) * (N_NODES / 128 + 1) / 2;   // 2080
    k_zzt<<<ntiles * 2, 256, ZZT_SMEM_BYTES>>>(out);
}

// round 11
// speedup vs baseline: 1.1939x; 1.0068x over previous
#include <cuda_runtime.h>
#include <cstdint>

#define N_NODES 8192
#define F_DIM   512
#define H1_DIM  32
#define H2_DIM  16
#define E_NNZ   131072

// ---------------- scratch (static device globals; no allocs) ----------------
__device__ __align__(16) float g_xw0[N_NODES * H1_DIM];   // X @ W0
__device__ __align__(16) float g_h1 [N_NODES * H1_DIM];   // spmm(A, XW0) (pre-relu)
__device__ __align__(16) float g_ah1[N_NODES * H1_DIM];   // spmm(A, relu(h1))
__device__ __align__(16) float g_z  [N_NODES * H2_DIM];   // final latent

// ---------------- helpers -----------------------------------------------------
__device__ __forceinline__ void red_add_v4(float* p, float a, float b, float c, float d) {
    asm volatile("red.global.add.v4.f32 [%0], {%1, %2, %3, %4};"
                 :: "l"(p), "f"(a), "f"(b), "f"(c), "f"(d) : "memory");
}
__device__ __forceinline__ void fma_f32x2(unsigned long long& d,
                                          unsigned long long a,
                                          unsigned long long b) {
    asm("fma.rn.f32x2 %0, %1, %2, %0;" : "+l"(d) : "l"(a), "l"(b));
}
__device__ __forceinline__ unsigned long long pack2(float x, float y) {
    unsigned long long u;
    asm("mov.b64 %0, {%1, %2};" : "=l"(u) : "f"(x), "f"(y));
    return u;
}

// ---------------- K1: XW0 = X @ W0, smem-tiled (32 rows/block, grid 256) -----
// Also zeros g_h1 + g_ah1 for the spmm stages.
__global__ void __launch_bounds__(256) k_xw0(const float* __restrict__ X,
                                             const float* __restrict__ W0) {
    __shared__ float sX [32 * 64];   // [row][k]
    __shared__ float sWp[32 * 64];   // [k_pair][col*2 + parity]
    int tid  = threadIdx.x;
    int wid  = tid >> 5;
    int lane = tid & 31;
    int row0 = blockIdx.x * 32;

    // pre-zero accumulators (32 rows x 32 floats = 256 float4 per buffer)
    {
        float4 z4 = make_float4(0.f, 0.f, 0.f, 0.f);
        reinterpret_cast<float4*>(g_h1  + (size_t)row0 * 32)[tid] = z4;
        reinterpret_cast<float4*>(g_ah1 + (size_t)row0 * 32)[tid] = z4;
    }

    unsigned long long acc[4];
#pragma unroll
    for (int r = 0; r < 4; r++) acc[r] = 0ull;

    for (int k0 = 0; k0 < F_DIM; k0 += 64) {
        __syncthreads();
        // X chunk: 32 rows x 64 k = 512 float4, 2/thread
#pragma unroll
        for (int q = 0; q < 2; q++) {
            int idx = q * 256 + tid;
            int r   = idx >> 4;
            int c4  = idx & 15;
            float4 v = *reinterpret_cast<const float4*>(
                &X[(size_t)(row0 + r) * F_DIM + k0 + c4 * 4]);
            *reinterpret_cast<float4*>(&sX[r * 64 + c4 * 4]) = v;
        }
        // W0 chunk: 512 float4, 2/thread, scattered into k-pair layout
#pragma unroll
        for (int q = 0; q < 2; q++) {
            int idx = q * 256 + tid;
            int kk  = idx >> 3;
            int c4  = idx & 7;
            float4 v = *reinterpret_cast<const float4*>(
                &W0[(size_t)(k0 + kk) * H1_DIM + c4 * 4]);
            int k2 = kk >> 1, par = kk & 1;
            float* b = &sWp[k2 * 64 + par];
            b[(4 * c4 + 0) * 2] = v.x;
            b[(4 * c4 + 1) * 2] = v.y;
            b[(4 * c4 + 2) * 2] = v.z;
            b[(4 * c4 + 3) * 2] = v.w;
        }
        __syncthreads();

#pragma unroll
        for (int pp = 0; pp < 16; pp++) {
            unsigned long long wa = *reinterpret_cast<const unsigned long long*>(
                &sWp[(2 * pp + 0) * 64 + 2 * lane]);
            unsigned long long wb = *reinterpret_cast<const unsigned long long*>(
                &sWp[(2 * pp + 1) * 64 + 2 * lane]);
#pragma unroll
            for (int r = 0; r < 4; r++) {
                float4 xv = *reinterpret_cast<const float4*>(
                    &sX[(wid * 4 + r) * 64 + 4 * pp]);
                fma_f32x2(acc[r], pack2(xv.x, xv.y), wa);
                fma_f32x2(acc[r], pack2(xv.z, xv.w), wb);
            }
        }
    }

#pragma unroll
    for (int r = 0; r < 4; r++) {
        unsigned long long u = acc[r];
        float lo = __int_as_float((int)(u & 0xffffffffull));
        float hi = __int_as_float((int)(u >> 32));
        g_xw0[(size_t)(row0 + wid * 4 + r) * H1_DIM + lane] = lo + hi;
    }
}

// ---------------- K2: h1 = spmm(A, XW0)  (8 threads/edge, red.v4) ----------
__global__ void k_spmm1(const int* __restrict__ rows, const int* __restrict__ cols,
                        const float* __restrict__ vals) {
    unsigned t = blockIdx.x * blockDim.x + threadIdx.x;    // < E*8
    unsigned e = t >> 3;
    unsigned s = t & 7;
    if (e >= E_NNZ) return;
    int r = rows[e];
    int c = cols[e];
    float v = vals[e];
    float4 x = *reinterpret_cast<const float4*>(&g_xw0[c * H1_DIM + s * 4]);
    red_add_v4(&g_h1[r * H1_DIM + s * 4], v * x.x, v * x.y, v * x.z, v * x.w);
}

// ---------------- K3: ah1 = spmm(A, relu(h1))  (8 threads/edge, red.v4) ----
__global__ void k_spmm2(const int* __restrict__ rows, const int* __restrict__ cols,
                        const float* __restrict__ vals) {
    unsigned t = blockIdx.x * blockDim.x + threadIdx.x;    // < E*8
    unsigned e = t >> 3;
    unsigned s = t & 7;
    if (e >= E_NNZ) return;
    int r = rows[e];
    int c = cols[e];
    float v = vals[e];
    float4 x = *reinterpret_cast<const float4*>(&g_h1[c * H1_DIM + s * 4]);
    red_add_v4(&g_ah1[r * H1_DIM + s * 4],
               v * fmaxf(x.x, 0.f), v * fmaxf(x.y, 0.f),
               v * fmaxf(x.z, 0.f), v * fmaxf(x.w, 0.f));
}

// ---------------- K4: fused heads: t = ah1@[W1|W2|W3], softmax, reparam ----
// Valid because spmm(A, h1@Wk) == (spmm(A, h1))@Wk  (associativity).
// ILP form: row preloaded into registers via 8 LDS.128 (broadcast), 6
// accumulators (2 per head) to halve the dependency-chain depth.
__global__ void __launch_bounds__(256) k_fuse(
        const float* __restrict__ W1, const float* __restrict__ W2,
        const float* __restrict__ W3,
        const float* __restrict__ s1, const float* __restrict__ s2) {
    __shared__ float sW[32 * 48];
    __shared__ float srow[16 * 32];
    int tid = threadIdx.x;
    for (int i = tid; i < 32 * 16; i += 256) {
        int k = i >> 4, j = i & 15;
        sW[k * 48 + j]      = W1[i];
        sW[k * 48 + 16 + j] = W2[i];
        sW[k * 48 + 32 + j] = W3[i];
    }
    int row0 = blockIdx.x * 16;
    if (tid < 128) {
        int r  = tid >> 3;
        int c4 = (tid & 7) * 4;
        *reinterpret_cast<float4*>(&srow[r * 32 + c4]) =
            *reinterpret_cast<const float4*>(&g_ah1[(size_t)(row0 + r) * 32 + c4]);
    }
    __syncthreads();

    int rr = tid >> 4;     // local row 0..15
    int l  = tid & 15;     // output col 0..15

    // preload row into registers (8x LDS.128, broadcast within 16-lane group)
    float rv[32];
#pragma unroll
    for (int q = 0; q < 8; q++) {
        float4 v = *reinterpret_cast<const float4*>(&srow[rr * 32 + 4 * q]);
        rv[4 * q + 0] = v.x;
        rv[4 * q + 1] = v.y;
        rv[4 * q + 2] = v.z;
        rv[4 * q + 3] = v.w;
    }

    float a1 = 0.f, b1 = 0.f, a2 = 0.f, b2 = 0.f, a3 = 0.f, b3 = 0.f;
#pragma unroll
    for (int k = 0; k < 32; k += 2) {
        float v0 = rv[k], v1 = rv[k + 1];
        a1 = fmaf(v0, sW[k * 48 + l],            a1);
        b1 = fmaf(v1, sW[(k + 1) * 48 + l],      b1);
        a2 = fmaf(v0, sW[k * 48 + 16 + l],       a2);
        b2 = fmaf(v1, sW[(k + 1) * 48 + 16 + l], b2);
        a3 = fmaf(v0, sW[k * 48 + 32 + l],       a3);
        b3 = fmaf(v1, sW[(k + 1) * 48 + 32 + l], b3);
    }
    a1 += b1; a2 += b2; a3 += b3;

    float m2 = a2, m3 = a3;
#pragma unroll
    for (int d = 8; d; d >>= 1) {
        m2 = fmaxf(m2, __shfl_xor_sync(0xffffffffu, m2, d));
        m3 = fmaxf(m3, __shfl_xor_sync(0xffffffffu, m3, d));
    }
    float e2 = __expf(a2 - m2), e3 = __expf(a3 - m3);
    float q2 = e2, q3 = e3;
#pragma unroll
    for (int d = 8; d; d >>= 1) {
        q2 += __shfl_xor_sync(0xffffffffu, q2, d);
        q3 += __shfl_xor_sync(0xffffffffu, q3, d);
    }
    float p2 = e2 / q2;          // z_log_en
    float p3 = e3 / q3;          // z_log_he
    int row = row0 + rr;
    float z_enn = __expf(p2) + s1[row * 16 + l] * (0.1f * __expf(p3));
    g_z[row * 16 + l] = a1 + s2[row * 16 + l] * z_enn;
}

// ---------------- K6: out = z @ z^T, 128x64 tiles, occ=2, __stcs stores ----
#define ZPAD   18
#define SM_STR 132    // 33 vecs
#define ZZT_SMEM_BYTES (64 * SM_STR * 4)   // 33792; compute phase needs 13824

__global__ void __launch_bounds__(256, 2) k_zzt(float* __restrict__ out) {
    extern __shared__ float sm[];
    float* szi  = sm;                       // [128][ZPAD] (compute phase)
    float* szj  = sm + 128 * ZPAD;          // [64][ZPAD]
    float* sm_m = sm;                       // [64][SM_STR] (staging, overlaps)

    // block -> (lower-tri square tile l, half h)
    int bx = blockIdx.x;
    int l  = bx >> 1;
    int h  = bx & 1;
    float f = sqrtf(8.0f * (float)l + 1.0f);
    int bi = (int)((f - 1.0f) * 0.5f);
    while ((bi + 1) * (bi + 2) / 2 <= l) bi++;
    while (bi * (bi + 1) / 2 > l) bi--;
    int bj = l - bi * (bi + 1) / 2;

    int i0 = bi * 128;
    int j0 = bj * 128 + h * 64;
    int tid = threadIdx.x;

    // load z tiles
#pragma unroll
    for (int q = 0; q < 2; q++) {
        int idx = q * 256 + tid;
        int r = idx >> 2;
        int c = (idx & 3) * 4;
        float4 vi = *reinterpret_cast<const float4*>(&g_z[(i0 + r) * 16 + c]);
        *reinterpret_cast<float2*>(&szi[r * ZPAD + c])     = make_float2(vi.x, vi.y);
        *reinterpret_cast<float2*>(&szi[r * ZPAD + c + 2]) = make_float2(vi.z, vi.w);
    }
    {
        int r = tid >> 2;
        int c = (tid & 3) * 4;
        float4 vj = *reinterpret_cast<const float4*>(&g_z[(j0 + r) * 16 + c]);
        *reinterpret_cast<float2*>(&szj[r * ZPAD + c])     = make_float2(vj.x, vj.y);
        *reinterpret_cast<float2*>(&szj[r * ZPAD + c + 2]) = make_float2(vj.z, vj.w);
    }
    __syncthreads();

    int ti = tid >> 4;    // 0..15 : rows ti+16r
    int tj = tid & 15;    // 0..15 : cols tj+16c (c<4)

    unsigned long long acc[8][4];
#pragma unroll
    for (int r = 0; r < 8; r++)
#pragma unroll
        for (int c = 0; c < 4; c++) acc[r][c] = 0ull;

#pragma unroll
    for (int kp = 0; kp < 8; kp++) {
        unsigned long long a[8], b[4];
#pragma unroll
        for (int r = 0; r < 8; r++)
            a[r] = *reinterpret_cast<const unsigned long long*>(
                &szi[(ti + 16 * r) * ZPAD + 2 * kp]);
#pragma unroll
        for (int c = 0; c < 4; c++)
            b[c] = *reinterpret_cast<const unsigned long long*>(
                &szj[(tj + 16 * c) * ZPAD + 2 * kp]);
#pragma unroll
        for (int r = 0; r < 8; r++)
#pragma unroll
            for (int c = 0; c < 4; c++) fma_f32x2(acc[r][c], a[r], b[c]);
    }

    bool mirror = (bi != bj);

    // finalize values; store direct tile straight from registers (streaming)
    float res[8][4];
#pragma unroll
    for (int r = 0; r < 8; r++)
#pragma unroll
        for (int c = 0; c < 4; c++) {
            unsigned long long u = acc[r][c];
            float lo = __int_as_float((int)(u & 0xffffffffull));
            float hi = __int_as_float((int)(u >> 32));
            res[r][c] = lo + hi;
            __stcs(&out[(size_t)(i0 + ti + 16 * r) * N_NODES + j0 + tj + 16 * c],
                   res[r][c]);
        }

    // mirror tile via smem transpose staging
    if (mirror) {
        __syncthreads();    // compute-phase smem reads done before overwrite
#pragma unroll
        for (int r = 0; r < 8; r++)
#pragma unroll
            for (int c = 0; c < 4; c++)
                sm_m[(tj + 16 * c) * SM_STR + ti + 16 * r] = res[r][c];
        __syncthreads();

        int lane = tid & 31;
        int w    = tid >> 5;   // 0..7
#pragma unroll
        for (int m = 0; m < 8; m++) {
            int j = 8 * w + m;
            float4 v = *reinterpret_cast<const float4*>(&sm_m[j * SM_STR + 4 * lane]);
            __stcs(reinterpret_cast<float4*>(
                       &out[(size_t)(j0 + j) * N_NODES + i0 + 4 * lane]), v);
        }
    }
}

// ---------------- launcher ---------------------------------------------------
extern "C" void kernel_launch(void* const* d_in, const int* in_sizes, int n_in,
                              void* d_out, int out_size) {
    const float* features = (const float*)d_in[0];
    const int*   adj_rows = (const int*)  d_in[1];
    const int*   adj_cols = (const int*)  d_in[2];
    const float* adj_val  = (const float*)d_in[3];
    const float* W0       = (const float*)d_in[4];
    const float* W1       = (const float*)d_in[5];
    const float* W2       = (const float*)d_in[6];
    const float* W3       = (const float*)d_in[7];
    const float* sample_1 = (const float*)d_in[8];
    const float* sample_2 = (const float*)d_in[9];
    float* out = (float*)d_out;

    cudaFuncSetAttribute(k_zzt, cudaFuncAttributeMaxDynamicSharedMemorySize,
                         ZZT_SMEM_BYTES);

    k_xw0  <<<N_NODES / 32, 256>>>(features, W0);
    k_spmm1<<<E_NNZ * 8 / 256, 256>>>(adj_rows, adj_cols, adj_val);
    k_spmm2<<<E_NNZ * 8 / 256, 256>>>(adj_rows, adj_cols, adj_val);
    k_fuse <<<N_NODES / 16, 256>>>(W1, W2, W3, sample_1, sample_2);

    int ntiles = (N_NODES / 128) * (N_NODES / 128 + 1) / 2;   // 2080
    k_zzt<<<ntiles * 2, 256, ZZT_SMEM_BYTES>>>(out);
}

// round 12
// speedup vs baseline: 1.2369x; 1.0361x over previous
#include <cuda_runtime.h>
#include <cstdint>

#define N_NODES 8192
#define F_DIM   512
#define H1_DIM  32
#define H2_DIM  16
#define E_NNZ   131072

// ---------------- scratch (static device globals; no allocs) ----------------
__device__ __align__(16) float g_xw0[N_NODES * H1_DIM];   // X @ W0
__device__ __align__(16) float g_h1 [N_NODES * H1_DIM];   // spmm(A, XW0) (pre-relu)
__device__ __align__(16) float g_ah1[N_NODES * H1_DIM];   // spmm(A, relu(h1))
__device__ __align__(16) float g_z  [N_NODES * H2_DIM];   // final latent

// ---------------- helpers -----------------------------------------------------
__device__ __forceinline__ void red_add_v4(float* p, float a, float b, float c, float d) {
    asm volatile("red.global.add.v4.f32 [%0], {%1, %2, %3, %4};"
                 :: "l"(p), "f"(a), "f"(b), "f"(c), "f"(d) : "memory");
}
__device__ __forceinline__ void fma_f32x2(unsigned long long& d,
                                          unsigned long long a,
                                          unsigned long long b) {
    asm("fma.rn.f32x2 %0, %1, %2, %0;" : "+l"(d) : "l"(a), "l"(b));
}
__device__ __forceinline__ unsigned long long pack2(float x, float y) {
    unsigned long long u;
    asm("mov.b64 %0, {%1, %2};" : "=l"(u) : "f"(x), "f"(y));
    return u;
}

// ---------------- K1: XW0 = X @ W0, smem-tiled (32 rows/block, grid 256) -----
__global__ void __launch_bounds__(256) k_xw0(const float* __restrict__ X,
                                             const float* __restrict__ W0) {
    __shared__ float sX [32 * 64];   // [row][k]
    __shared__ float sWp[32 * 64];   // [k_pair][col*2 + parity]
    int tid  = threadIdx.x;
    int wid  = tid >> 5;
    int lane = tid & 31;
    int row0 = blockIdx.x * 32;

    // pre-zero accumulators (32 rows x 32 floats = 256 float4 per buffer)
    {
        float4 z4 = make_float4(0.f, 0.f, 0.f, 0.f);
        reinterpret_cast<float4*>(g_h1  + (size_t)row0 * 32)[tid] = z4;
        reinterpret_cast<float4*>(g_ah1 + (size_t)row0 * 32)[tid] = z4;
    }

    unsigned long long acc[4];
#pragma unroll
    for (int r = 0; r < 4; r++) acc[r] = 0ull;

    for (int k0 = 0; k0 < F_DIM; k0 += 64) {
        __syncthreads();
#pragma unroll
        for (int q = 0; q < 2; q++) {
            int idx = q * 256 + tid;
            int r   = idx >> 4;
            int c4  = idx & 15;
            float4 v = *reinterpret_cast<const float4*>(
                &X[(size_t)(row0 + r) * F_DIM + k0 + c4 * 4]);
            *reinterpret_cast<float4*>(&sX[r * 64 + c4 * 4]) = v;
        }
#pragma unroll
        for (int q = 0; q < 2; q++) {
            int idx = q * 256 + tid;
            int kk  = idx >> 3;
            int c4  = idx & 7;
            float4 v = *reinterpret_cast<const float4*>(
                &W0[(size_t)(k0 + kk) * H1_DIM + c4 * 4]);
            int k2 = kk >> 1, par = kk & 1;
            float* b = &sWp[k2 * 64 + par];
            b[(4 * c4 + 0) * 2] = v.x;
            b[(4 * c4 + 1) * 2] = v.y;
            b[(4 * c4 + 2) * 2] = v.z;
            b[(4 * c4 + 3) * 2] = v.w;
        }
        __syncthreads();

#pragma unroll
        for (int pp = 0; pp < 16; pp++) {
            unsigned long long wa = *reinterpret_cast<const unsigned long long*>(
                &sWp[(2 * pp + 0) * 64 + 2 * lane]);
            unsigned long long wb = *reinterpret_cast<const unsigned long long*>(
                &sWp[(2 * pp + 1) * 64 + 2 * lane]);
#pragma unroll
            for (int r = 0; r < 4; r++) {
                float4 xv = *reinterpret_cast<const float4*>(
                    &sX[(wid * 4 + r) * 64 + 4 * pp]);
                fma_f32x2(acc[r], pack2(xv.x, xv.y), wa);
                fma_f32x2(acc[r], pack2(xv.z, xv.w), wb);
            }
        }
    }

#pragma unroll
    for (int r = 0; r < 4; r++) {
        unsigned long long u = acc[r];
        float lo = __int_as_float((int)(u & 0xffffffffull));
        float hi = __int_as_float((int)(u >> 32));
        g_xw0[(size_t)(row0 + wid * 4 + r) * H1_DIM + lane] = lo + hi;
    }
}

// ---------------- K2: h1 = spmm(A, XW0)  (8 threads/edge, red.v4) ----------
__global__ void k_spmm1(const int* __restrict__ rows, const int* __restrict__ cols,
                        const float* __restrict__ vals) {
    unsigned t = blockIdx.x * blockDim.x + threadIdx.x;    // < E*8
    unsigned e = t >> 3;
    unsigned s = t & 7;
    if (e >= E_NNZ) return;
    int r = rows[e];
    int c = cols[e];
    float v = vals[e];
    float4 x = *reinterpret_cast<const float4*>(&g_xw0[c * H1_DIM + s * 4]);
    red_add_v4(&g_h1[r * H1_DIM + s * 4], v * x.x, v * x.y, v * x.z, v * x.w);
}

// ---------------- K3: ah1 = spmm(A, relu(h1))  (8 threads/edge, red.v4) ----
__global__ void k_spmm2(const int* __restrict__ rows, const int* __restrict__ cols,
                        const float* __restrict__ vals) {
    unsigned t = blockIdx.x * blockDim.x + threadIdx.x;    // < E*8
    unsigned e = t >> 3;
    unsigned s = t & 7;
    if (e >= E_NNZ) return;
    int r = rows[e];
    int c = cols[e];
    float v = vals[e];
    float4 x = *reinterpret_cast<const float4*>(&g_h1[c * H1_DIM + s * 4]);
    red_add_v4(&g_ah1[r * H1_DIM + s * 4],
               v * fmaxf(x.x, 0.f), v * fmaxf(x.y, 0.f),
               v * fmaxf(x.z, 0.f), v * fmaxf(x.w, 0.f));
}

// ---------------- K4: fused heads: t = ah1@[W1|W2|W3], softmax, reparam ----
// Valid because spmm(A, h1@Wk) == (spmm(A, h1))@Wk  (associativity).
// R8 lean form + __fdividef for the softmax normalizations.
__global__ void __launch_bounds__(256) k_fuse(
        const float* __restrict__ W1, const float* __restrict__ W2,
        const float* __restrict__ W3,
        const float* __restrict__ s1, const float* __restrict__ s2) {
    __shared__ float sW[32 * 48];
    __shared__ float srow[16 * 32];
    int tid = threadIdx.x;
    for (int i = tid; i < 32 * 16; i += 256) {
        int k = i >> 4, j = i & 15;
        sW[k * 48 + j]      = W1[i];
        sW[k * 48 + 16 + j] = W2[i];
        sW[k * 48 + 32 + j] = W3[i];
    }
    int row0 = blockIdx.x * 16;
    if (tid < 128) {
        int r  = tid >> 3;
        int c4 = (tid & 7) * 4;
        *reinterpret_cast<float4*>(&srow[r * 32 + c4]) =
            *reinterpret_cast<const float4*>(&g_ah1[(size_t)(row0 + r) * 32 + c4]);
    }
    __syncthreads();

    int rr = tid >> 4;     // local row 0..15
    int l  = tid & 15;     // output col 0..15
    float a1 = 0.f, a2 = 0.f, a3 = 0.f;
#pragma unroll
    for (int k = 0; k < 32; k++) {
        float v = srow[rr * 32 + k];
        a1 = fmaf(v, sW[k * 48 + l],      a1);
        a2 = fmaf(v, sW[k * 48 + 16 + l], a2);
        a3 = fmaf(v, sW[k * 48 + 32 + l], a3);
    }

    float m2 = a2, m3 = a3;
#pragma unroll
    for (int d = 8; d; d >>= 1) {
        m2 = fmaxf(m2, __shfl_xor_sync(0xffffffffu, m2, d));
        m3 = fmaxf(m3, __shfl_xor_sync(0xffffffffu, m3, d));
    }
    float e2 = __expf(a2 - m2), e3 = __expf(a3 - m3);
    float q2 = e2, q3 = e3;
#pragma unroll
    for (int d = 8; d; d >>= 1) {
        q2 += __shfl_xor_sync(0xffffffffu, q2, d);
        q3 += __shfl_xor_sync(0xffffffffu, q3, d);
    }
    float p2 = __fdividef(e2, q2);          // z_log_en
    float p3 = __fdividef(e3, q3);          // z_log_he
    int row = row0 + rr;
    float z_enn = __expf(p2) + s1[row * 16 + l] * (0.1f * __expf(p3));
    g_z[row * 16 + l] = a1 + s2[row * 16 + l] * z_enn;
}

// ---------------- K6: out = z @ z^T, 128x32 tiles, occ=3, __stcs stores ----
// Quarter-tiles of the lower-tri 128x128 squares: acc = 8x2 f32x2 (32 regs)
// -> 3 blocks/SM (24 warps) for better latency hiding; FLOPs are tile-size
// invariant for this GEMM so the extra blocks are free.
#define ZPAD   18
#define SM_STR 132    // 33 vecs
#define ZZT_SMEM_BYTES (32 * SM_STR * 4)   // 16896; compute phase needs 11520

__global__ void __launch_bounds__(256, 3) k_zzt(float* __restrict__ out) {
    extern __shared__ float sm[];
    float* szi  = sm;                       // [128][ZPAD] (compute phase)
    float* szj  = sm + 128 * ZPAD;          // [32][ZPAD]
    float* sm_m = sm;                       // [32][SM_STR] (staging, overlaps)

    // block -> (lower-tri square tile l, quarter h)
    int bx = blockIdx.x;
    int l  = bx >> 2;
    int h  = bx & 3;
    float f = sqrtf(8.0f * (float)l + 1.0f);
    int bi = (int)((f - 1.0f) * 0.5f);
    while ((bi + 1) * (bi + 2) / 2 <= l) bi++;
    while (bi * (bi + 1) / 2 > l) bi--;
    int bj = l - bi * (bi + 1) / 2;

    int i0 = bi * 128;
    int j0 = bj * 128 + h * 32;
    int tid = threadIdx.x;

    // load z tiles: szi 128x16 (512 float4, 2/thread); szj 32x16 (128 float4)
#pragma unroll
    for (int q = 0; q < 2; q++) {
        int idx = q * 256 + tid;
        int r = idx >> 2;
        int c = (idx & 3) * 4;
        float4 vi = *reinterpret_cast<const float4*>(&g_z[(i0 + r) * 16 + c]);
        *reinterpret_cast<float2*>(&szi[r * ZPAD + c])     = make_float2(vi.x, vi.y);
        *reinterpret_cast<float2*>(&szi[r * ZPAD + c + 2]) = make_float2(vi.z, vi.w);
    }
    if (tid < 128) {
        int r = tid >> 2;
        int c = (tid & 3) * 4;
        float4 vj = *reinterpret_cast<const float4*>(&g_z[(j0 + r) * 16 + c]);
        *reinterpret_cast<float2*>(&szj[r * ZPAD + c])     = make_float2(vj.x, vj.y);
        *reinterpret_cast<float2*>(&szj[r * ZPAD + c + 2]) = make_float2(vj.z, vj.w);
    }
    __syncthreads();

    int ti = tid >> 4;    // 0..15 : rows ti+16r (r<8)
    int tj = tid & 15;    // 0..15 : cols tj+16c (c<2)

    unsigned long long acc[8][2];
#pragma unroll
    for (int r = 0; r < 8; r++)
#pragma unroll
        for (int c = 0; c < 2; c++) acc[r][c] = 0ull;

#pragma unroll
    for (int kp = 0; kp < 8; kp++) {
        unsigned long long a[8], b[2];
#pragma unroll
        for (int r = 0; r < 8; r++)
            a[r] = *reinterpret_cast<const unsigned long long*>(
                &szi[(ti + 16 * r) * ZPAD + 2 * kp]);
#pragma unroll
        for (int c = 0; c < 2; c++)
            b[c] = *reinterpret_cast<const unsigned long long*>(
                &szj[(tj + 16 * c) * ZPAD + 2 * kp]);
#pragma unroll
        for (int r = 0; r < 8; r++)
#pragma unroll
            for (int c = 0; c < 2; c++) fma_f32x2(acc[r][c], a[r], b[c]);
    }

    bool mirror = (bi != bj);

    // finalize; store direct tile straight from registers (streaming)
    float res[8][2];
#pragma unroll
    for (int r = 0; r < 8; r++)
#pragma unroll
        for (int c = 0; c < 2; c++) {
            unsigned long long u = acc[r][c];
            float lo = __int_as_float((int)(u & 0xffffffffull));
            float hi = __int_as_float((int)(u >> 32));
            res[r][c] = lo + hi;
            __stcs(&out[(size_t)(i0 + ti + 16 * r) * N_NODES + j0 + tj + 16 * c],
                   res[r][c]);
        }

    // mirror tile via smem transpose staging
    if (mirror) {
        __syncthreads();    // compute-phase smem reads done before overwrite
#pragma unroll
        for (int r = 0; r < 8; r++)
#pragma unroll
            for (int c = 0; c < 2; c++)
                sm_m[(tj + 16 * c) * SM_STR + ti + 16 * r] = res[r][c];
        __syncthreads();

        int lane = tid & 31;
        int w    = tid >> 5;   // 0..7, warp handles rows 4w..4w+3
#pragma unroll
        for (int m = 0; m < 4; m++) {
            int j = 4 * w + m;
            float4 v = *reinterpret_cast<const float4*>(&sm_m[j * SM_STR + 4 * lane]);
            __stcs(reinterpret_cast<float4*>(
                       &out[(size_t)(j0 + j) * N_NODES + i0 + 4 * lane]), v);
        }
    }
}

// ---------------- launcher ---------------------------------------------------
extern "C" void kernel_launch(void* const* d_in, const int* in_sizes, int n_in,
                              void* d_out, int out_size) {
    const float* features = (const float*)d_in[0];
    const int*   adj_rows = (const int*)  d_in[1];
    const int*   adj_cols = (const int*)  d_in[2];
    const float* adj_val  = (const float*)d_in[3];
    const float* W0       = (const float*)d_in[4];
    const float* W1       = (const float*)d_in[5];
    const float* W2       = (const float*)d_in[6];
    const float* W3       = (const float*)d_in[7];
    const float* sample_1 = (const float*)d_in[8];
    const float* sample_2 = (const float*)d_in[9];
    float* out = (float*)d_out;

    cudaFuncSetAttribute(k_zzt, cudaFuncAttributeMaxDynamicSharedMemorySize,
                         ZZT_SMEM_BYTES);

    k_xw0  <<<N_NODES / 32, 256>>>(features, W0);
    k_spmm1<<<E_NNZ * 8 / 256, 256>>>(adj_rows, adj_cols, adj_val);
    k_spmm2<<<E_NNZ * 8 / 256, 256>>>(adj_rows, adj_cols, adj_val);
    k_fuse <<<N_NODES / 16, 256>>>(W1, W2, W3, sample_1, sample_2);

    int ntiles = (N_NODES / 128) * (N_NODES / 128 + 1) / 2;   // 2080
    k_zzt<<<ntiles * 4, 256, ZZT_SMEM_BYTES>>>(out);
}

// round 13
// speedup vs baseline: 1.2556x; 1.0151x over previous
#include <cuda_runtime.h>
#include <cstdint>

#define N_NODES 8192
#define F_DIM   512
#define H1_DIM  32
#define H2_DIM  16
#define E_NNZ   131072

// ---------------- scratch (static device globals; no allocs) ----------------
__device__ __align__(16) float g_xw0[N_NODES * H1_DIM];   // X @ W0
__device__ __align__(16) float g_h1 [N_NODES * H1_DIM];   // spmm(A, XW0) (pre-relu)
__device__ __align__(16) float g_ah1[N_NODES * H1_DIM];   // spmm(A, relu(h1))
__device__ __align__(16) float g_z  [N_NODES * H2_DIM];   // final latent

// ---------------- helpers -----------------------------------------------------
__device__ __forceinline__ void red_add_v4(float* p, float a, float b, float c, float d) {
    asm volatile("red.global.add.v4.f32 [%0], {%1, %2, %3, %4};"
                 :: "l"(p), "f"(a), "f"(b), "f"(c), "f"(d) : "memory");
}
__device__ __forceinline__ void fma_f32x2(unsigned long long& d,
                                          unsigned long long a,
                                          unsigned long long b) {
    asm("fma.rn.f32x2 %0, %1, %2, %0;" : "+l"(d) : "l"(a), "l"(b));
}
__device__ __forceinline__ unsigned long long pack2(float x, float y) {
    unsigned long long u;
    asm("mov.b64 %0, {%1, %2};" : "=l"(u) : "f"(x), "f"(y));
    return u;
}

// ---------------- K1: XW0 = X @ W0, smem-tiled (32 rows/block, grid 256) -----
__global__ void __launch_bounds__(256) k_xw0(const float* __restrict__ X,
                                             const float* __restrict__ W0) {
    __shared__ float sX [32 * 64];   // [row][k]
    __shared__ float sWp[32 * 64];   // [k_pair][col*2 + parity]
    int tid  = threadIdx.x;
    int wid  = tid >> 5;
    int lane = tid & 31;
    int row0 = blockIdx.x * 32;

    // pre-zero accumulators (32 rows x 32 floats = 256 float4 per buffer)
    {
        float4 z4 = make_float4(0.f, 0.f, 0.f, 0.f);
        reinterpret_cast<float4*>(g_h1  + (size_t)row0 * 32)[tid] = z4;
        reinterpret_cast<float4*>(g_ah1 + (size_t)row0 * 32)[tid] = z4;
    }

    unsigned long long acc[4];
#pragma unroll
    for (int r = 0; r < 4; r++) acc[r] = 0ull;

    for (int k0 = 0; k0 < F_DIM; k0 += 64) {
        __syncthreads();
#pragma unroll
        for (int q = 0; q < 2; q++) {
            int idx = q * 256 + tid;
            int r   = idx >> 4;
            int c4  = idx & 15;
            float4 v = *reinterpret_cast<const float4*>(
                &X[(size_t)(row0 + r) * F_DIM + k0 + c4 * 4]);
            *reinterpret_cast<float4*>(&sX[r * 64 + c4 * 4]) = v;
        }
#pragma unroll
        for (int q = 0; q < 2; q++) {
            int idx = q * 256 + tid;
            int kk  = idx >> 3;
            int c4  = idx & 7;
            float4 v = *reinterpret_cast<const float4*>(
                &W0[(size_t)(k0 + kk) * H1_DIM + c4 * 4]);
            int k2 = kk >> 1, par = kk & 1;
            float* b = &sWp[k2 * 64 + par];
            b[(4 * c4 + 0) * 2] = v.x;
            b[(4 * c4 + 1) * 2] = v.y;
            b[(4 * c4 + 2) * 2] = v.z;
            b[(4 * c4 + 3) * 2] = v.w;
        }
        __syncthreads();

#pragma unroll
        for (int pp = 0; pp < 16; pp++) {
            unsigned long long wa = *reinterpret_cast<const unsigned long long*>(
                &sWp[(2 * pp + 0) * 64 + 2 * lane]);
            unsigned long long wb = *reinterpret_cast<const unsigned long long*>(
                &sWp[(2 * pp + 1) * 64 + 2 * lane]);
#pragma unroll
            for (int r = 0; r < 4; r++) {
                float4 xv = *reinterpret_cast<const float4*>(
                    &sX[(wid * 4 + r) * 64 + 4 * pp]);
                fma_f32x2(acc[r], pack2(xv.x, xv.y), wa);
                fma_f32x2(acc[r], pack2(xv.z, xv.w), wb);
            }
        }
    }

#pragma unroll
    for (int r = 0; r < 4; r++) {
        unsigned long long u = acc[r];
        float lo = __int_as_float((int)(u & 0xffffffffull));
        float hi = __int_as_float((int)(u >> 32));
        g_xw0[(size_t)(row0 + wid * 4 + r) * H1_DIM + lane] = lo + hi;
    }
}

// ---------------- K2: h1 = spmm(A, XW0)  (8 threads/edge, red.v4) ----------
__global__ void k_spmm1(const int* __restrict__ rows, const int* __restrict__ cols,
                        const float* __restrict__ vals) {
    unsigned t = blockIdx.x * blockDim.x + threadIdx.x;    // < E*8
    unsigned e = t >> 3;
    unsigned s = t & 7;
    if (e >= E_NNZ) return;
    int r = rows[e];
    int c = cols[e];
    float v = vals[e];
    float4 x = *reinterpret_cast<const float4*>(&g_xw0[c * H1_DIM + s * 4]);
    red_add_v4(&g_h1[r * H1_DIM + s * 4], v * x.x, v * x.y, v * x.z, v * x.w);
}

// ---------------- K3: ah1 = spmm(A, relu(h1))  (8 threads/edge, red.v4) ----
__global__ void k_spmm2(const int* __restrict__ rows, const int* __restrict__ cols,
                        const float* __restrict__ vals) {
    unsigned t = blockIdx.x * blockDim.x + threadIdx.x;    // < E*8
    unsigned e = t >> 3;
    unsigned s = t & 7;
    if (e >= E_NNZ) return;
    int r = rows[e];
    int c = cols[e];
    float v = vals[e];
    float4 x = *reinterpret_cast<const float4*>(&g_h1[c * H1_DIM + s * 4]);
    red_add_v4(&g_ah1[r * H1_DIM + s * 4],
               v * fmaxf(x.x, 0.f), v * fmaxf(x.y, 0.f),
               v * fmaxf(x.z, 0.f), v * fmaxf(x.w, 0.f));
}

// ---------------- K4: fused heads: t = ah1@[W1|W2|W3], softmax, reparam ----
// Valid because spmm(A, h1@Wk) == (spmm(A, h1))@Wk  (associativity).
// 1024-thread blocks, 64 rows each (grid 128): quarters the per-block fixed
// cost (weight smem fill + sync) vs the 512-block version.
__global__ void __launch_bounds__(1024) k_fuse(
        const float* __restrict__ W1, const float* __restrict__ W2,
        const float* __restrict__ W3,
        const float* __restrict__ s1, const float* __restrict__ s2) {
    __shared__ float sW[32 * 48];
    __shared__ float srow[64 * 32];
    int tid = threadIdx.x;
    if (tid < 512) {
        int i = tid;
        int k = i >> 4, j = i & 15;
        sW[k * 48 + j]      = W1[i];
        sW[k * 48 + 16 + j] = W2[i];
        sW[k * 48 + 32 + j] = W3[i];
    }
    int row0 = blockIdx.x * 64;
    if (tid < 512) {
        int r  = tid >> 3;
        int c4 = (tid & 7) * 4;
        *reinterpret_cast<float4*>(&srow[r * 32 + c4]) =
            *reinterpret_cast<const float4*>(&g_ah1[(size_t)(row0 + r) * 32 + c4]);
    }
    __syncthreads();

    int rr = tid >> 4;     // local row 0..63
    int l  = tid & 15;     // output col 0..15
    float a1 = 0.f, a2 = 0.f, a3 = 0.f;
#pragma unroll
    for (int k = 0; k < 32; k++) {
        float v = srow[rr * 32 + k];
        a1 = fmaf(v, sW[k * 48 + l],      a1);
        a2 = fmaf(v, sW[k * 48 + 16 + l], a2);
        a3 = fmaf(v, sW[k * 48 + 32 + l], a3);
    }

    float m2 = a2, m3 = a3;
#pragma unroll
    for (int d = 8; d; d >>= 1) {
        m2 = fmaxf(m2, __shfl_xor_sync(0xffffffffu, m2, d));
        m3 = fmaxf(m3, __shfl_xor_sync(0xffffffffu, m3, d));
    }
    float e2 = __expf(a2 - m2), e3 = __expf(a3 - m3);
    float q2 = e2, q3 = e3;
#pragma unroll
    for (int d = 8; d; d >>= 1) {
        q2 += __shfl_xor_sync(0xffffffffu, q2, d);
        q3 += __shfl_xor_sync(0xffffffffu, q3, d);
    }
    float p2 = __fdividef(e2, q2);          // z_log_en
    float p3 = __fdividef(e3, q3);          // z_log_he
    int row = row0 + rr;
    float z_enn = __expf(p2) + s1[row * 16 + l] * (0.1f * __expf(p3));
    g_z[row * 16 + l] = a1 + s2[row * 16 + l] * z_enn;
}

// ---------------- K6: out = z @ z^T, 128x32 tiles, occ=4, __stcs stores ----
// acc = 8x2 f32x2 (32 regs) -> 4 blocks/SM (32 warps). smem 16.9KB x4 = 68KB.
#define ZPAD   18
#define SM_STR 132    // 33 vecs
#define ZZT_SMEM_BYTES (32 * SM_STR * 4)   // 16896; compute phase needs 11520

__global__ void __launch_bounds__(256, 4) k_zzt(float* __restrict__ out) {
    extern __shared__ float sm[];
    float* szi  = sm;                       // [128][ZPAD] (compute phase)
    float* szj  = sm + 128 * ZPAD;          // [32][ZPAD]
    float* sm_m = sm;                       // [32][SM_STR] (staging, overlaps)

    // block -> (lower-tri square tile l, quarter h)
    int bx = blockIdx.x;
    int l  = bx >> 2;
    int h  = bx & 3;
    float f = sqrtf(8.0f * (float)l + 1.0f);
    int bi = (int)((f - 1.0f) * 0.5f);
    while ((bi + 1) * (bi + 2) / 2 <= l) bi++;
    while (bi * (bi + 1) / 2 > l) bi--;
    int bj = l - bi * (bi + 1) / 2;

    int i0 = bi * 128;
    int j0 = bj * 128 + h * 32;
    int tid = threadIdx.x;

    // load z tiles: szi 128x16 (512 float4, 2/thread); szj 32x16 (128 float4)
#pragma unroll
    for (int q = 0; q < 2; q++) {
        int idx = q * 256 + tid;
        int r = idx >> 2;
        int c = (idx & 3) * 4;
        float4 vi = *reinterpret_cast<const float4*>(&g_z[(i0 + r) * 16 + c]);
        *reinterpret_cast<float2*>(&szi[r * ZPAD + c])     = make_float2(vi.x, vi.y);
        *reinterpret_cast<float2*>(&szi[r * ZPAD + c + 2]) = make_float2(vi.z, vi.w);
    }
    if (tid < 128) {
        int r = tid >> 2;
        int c = (tid & 3) * 4;
        float4 vj = *reinterpret_cast<const float4*>(&g_z[(j0 + r) * 16 + c]);
        *reinterpret_cast<float2*>(&szj[r * ZPAD + c])     = make_float2(vj.x, vj.y);
        *reinterpret_cast<float2*>(&szj[r * ZPAD + c + 2]) = make_float2(vj.z, vj.w);
    }
    __syncthreads();

    int ti = tid >> 4;    // 0..15 : rows ti+16r (r<8)
    int tj = tid & 15;    // 0..15 : cols tj+16c (c<2)

    unsigned long long acc[8][2];
#pragma unroll
    for (int r = 0; r < 8; r++)
#pragma unroll
        for (int c = 0; c < 2; c++) acc[r][c] = 0ull;

#pragma unroll
    for (int kp = 0; kp < 8; kp++) {
        unsigned long long a[8], b[2];
#pragma unroll
        for (int r = 0; r < 8; r++)
            a[r] = *reinterpret_cast<const unsigned long long*>(
                &szi[(ti + 16 * r) * ZPAD + 2 * kp]);
#pragma unroll
        for (int c = 0; c < 2; c++)
            b[c] = *reinterpret_cast<const unsigned long long*>(
                &szj[(tj + 16 * c) * ZPAD + 2 * kp]);
#pragma unroll
        for (int r = 0; r < 8; r++)
#pragma unroll
            for (int c = 0; c < 2; c++) fma_f32x2(acc[r][c], a[r], b[c]);
    }

    bool mirror = (bi != bj);

    // finalize; store direct tile straight from registers (streaming)
    float res[8][2];
#pragma unroll
    for (int r = 0; r < 8; r++)
#pragma unroll
        for (int c = 0; c < 2; c++) {
            unsigned long long u = acc[r][c];
            float lo = __int_as_float((int)(u & 0xffffffffull));
            float hi = __int_as_float((int)(u >> 32));
            res[r][c] = lo + hi;
            __stcs(&out[(size_t)(i0 + ti + 16 * r) * N_NODES + j0 + tj + 16 * c],
                   res[r][c]);
        }

    // mirror tile via smem transpose staging
    if (mirror) {
        __syncthreads();    // compute-phase smem reads done before overwrite
#pragma unroll
        for (int r = 0; r < 8; r++)
#pragma unroll
            for (int c = 0; c < 2; c++)
                sm_m[(tj + 16 * c) * SM_STR + ti + 16 * r] = res[r][c];
        __syncthreads();

        int lane = tid & 31;
        int w    = tid >> 5;   // 0..7, warp handles rows 4w..4w+3
#pragma unroll
        for (int m = 0; m < 4; m++) {
            int j = 4 * w + m;
            float4 v = *reinterpret_cast<const float4*>(&sm_m[j * SM_STR + 4 * lane]);
            __stcs(reinterpret_cast<float4*>(
                       &out[(size_t)(j0 + j) * N_NODES + i0 + 4 * lane]), v);
        }
    }
}

// ---------------- launcher ---------------------------------------------------
extern "C" void kernel_launch(void* const* d_in, const int* in_sizes, int n_in,
                              void* d_out, int out_size) {
    const float* features = (const float*)d_in[0];
    const int*   adj_rows = (const int*)  d_in[1];
    const int*   adj_cols = (const int*)  d_in[2];
    const float* adj_val  = (const float*)d_in[3];
    const float* W0       = (const float*)d_in[4];
    const float* W1       = (const float*)d_in[5];
    const float* W2       = (const float*)d_in[6];
    const float* W3       = (const float*)d_in[7];
    const float* sample_1 = (const float*)d_in[8];
    const float* sample_2 = (const float*)d_in[9];
    float* out = (float*)d_out;

    cudaFuncSetAttribute(k_zzt, cudaFuncAttributeMaxDynamicSharedMemorySize,
                         ZZT_SMEM_BYTES);

    k_xw0  <<<N_NODES / 32, 256>>>(features, W0);
    k_spmm1<<<E_NNZ * 8 / 256, 256>>>(adj_rows, adj_cols, adj_val);
    k_spmm2<<<E_NNZ * 8 / 256, 256>>>(adj_rows, adj_cols, adj_val);
    k_fuse <<<N_NODES / 64, 1024>>>(W1, W2, W3, sample_1, sample_2);

    int ntiles = (N_NODES / 128) * (N_NODES / 128 + 1) / 2;   // 2080
    k_zzt<<<ntiles * 4, 256, ZZT_SMEM_BYTES>>>(out);
}

// round 14
// speedup vs baseline: 1.2730x; 1.0139x over previous
#include <cuda_runtime.h>
#include <cstdint>

#define N_NODES 8192
#define F_DIM   512
#define H1_DIM  32
#define H2_DIM  16
#define E_NNZ   131072

// ---------------- scratch (static device globals; no allocs) ----------------
__device__ __align__(16) float g_xw0[N_NODES * H1_DIM];   // X @ W0
__device__ __align__(16) float g_h1 [N_NODES * H1_DIM];   // spmm(A, XW0) (pre-relu)
__device__ __align__(16) float g_ah1[N_NODES * H1_DIM];   // spmm(A, relu(h1))
__device__ __align__(16) float g_z  [N_NODES * H2_DIM];   // final latent

// ---------------- helpers -----------------------------------------------------
__device__ __forceinline__ void red_add_v4(float* p, float a, float b, float c, float d) {
    asm volatile("red.global.add.v4.f32 [%0], {%1, %2, %3, %4};"
                 :: "l"(p), "f"(a), "f"(b), "f"(c), "f"(d) : "memory");
}
__device__ __forceinline__ void fma_f32x2(unsigned long long& d,
                                          unsigned long long a,
                                          unsigned long long b) {
    asm("fma.rn.f32x2 %0, %1, %2, %0;" : "+l"(d) : "l"(a), "l"(b));
}
__device__ __forceinline__ unsigned long long pack2(float x, float y) {
    unsigned long long u;
    asm("mov.b64 %0, {%1, %2};" : "=l"(u) : "f"(x), "f"(y));
    return u;
}

// ---------------- K1: XW0 = X @ W0, smem-tiled (32 rows/block, grid 256) -----
__global__ void __launch_bounds__(256) k_xw0(const float* __restrict__ X,
                                             const float* __restrict__ W0) {
    __shared__ float sX [32 * 64];   // [row][k]
    __shared__ float sWp[32 * 64];   // [k_pair][col*2 + parity]
    int tid  = threadIdx.x;
    int wid  = tid >> 5;
    int lane = tid & 31;
    int row0 = blockIdx.x * 32;

    // pre-zero accumulators (32 rows x 32 floats = 256 float4 per buffer)
    {
        float4 z4 = make_float4(0.f, 0.f, 0.f, 0.f);
        reinterpret_cast<float4*>(g_h1  + (size_t)row0 * 32)[tid] = z4;
        reinterpret_cast<float4*>(g_ah1 + (size_t)row0 * 32)[tid] = z4;
    }

    unsigned long long acc[4];
#pragma unroll
    for (int r = 0; r < 4; r++) acc[r] = 0ull;

    for (int k0 = 0; k0 < F_DIM; k0 += 64) {
        __syncthreads();
#pragma unroll
        for (int q = 0; q < 2; q++) {
            int idx = q * 256 + tid;
            int r   = idx >> 4;
            int c4  = idx & 15;
            float4 v = *reinterpret_cast<const float4*>(
                &X[(size_t)(row0 + r) * F_DIM + k0 + c4 * 4]);
            *reinterpret_cast<float4*>(&sX[r * 64 + c4 * 4]) = v;
        }
#pragma unroll
        for (int q = 0; q < 2; q++) {
            int idx = q * 256 + tid;
            int kk  = idx >> 3;
            int c4  = idx & 7;
            float4 v = *reinterpret_cast<const float4*>(
                &W0[(size_t)(k0 + kk) * H1_DIM + c4 * 4]);
            int k2 = kk >> 1, par = kk & 1;
            float* b = &sWp[k2 * 64 + par];
            b[(4 * c4 + 0) * 2] = v.x;
            b[(4 * c4 + 1) * 2] = v.y;
            b[(4 * c4 + 2) * 2] = v.z;
            b[(4 * c4 + 3) * 2] = v.w;
        }
        __syncthreads();

#pragma unroll
        for (int pp = 0; pp < 16; pp++) {
            unsigned long long wa = *reinterpret_cast<const unsigned long long*>(
                &sWp[(2 * pp + 0) * 64 + 2 * lane]);
            unsigned long long wb = *reinterpret_cast<const unsigned long long*>(
                &sWp[(2 * pp + 1) * 64 + 2 * lane]);
#pragma unroll
            for (int r = 0; r < 4; r++) {
                float4 xv = *reinterpret_cast<const float4*>(
                    &sX[(wid * 4 + r) * 64 + 4 * pp]);
                fma_f32x2(acc[r], pack2(xv.x, xv.y), wa);
                fma_f32x2(acc[r], pack2(xv.z, xv.w), wb);
            }
        }
    }

#pragma unroll
    for (int r = 0; r < 4; r++) {
        unsigned long long u = acc[r];
        float lo = __int_as_float((int)(u & 0xffffffffull));
        float hi = __int_as_float((int)(u >> 32));
        g_xw0[(size_t)(row0 + wid * 4 + r) * H1_DIM + lane] = lo + hi;
    }
}

// ---------------- K2: h1 = spmm(A, XW0)  (2 edges/thread, 8 thr/edge) ------
__global__ void k_spmm1(const int* __restrict__ rows, const int* __restrict__ cols,
                        const float* __restrict__ vals) {
    unsigned t = blockIdx.x * blockDim.x + threadIdx.x;    // < (E/2)*8
    unsigned e = t >> 3;               // 0 .. E/2-1
    unsigned s = t & 7;
    unsigned e2 = e + E_NNZ / 2;

    int   r1 = rows[e],  c1 = cols[e];
    float v1 = vals[e];
    int   r2 = rows[e2], c2 = cols[e2];
    float v2 = vals[e2];

    float4 x1 = *reinterpret_cast<const float4*>(&g_xw0[c1 * H1_DIM + s * 4]);
    float4 x2 = *reinterpret_cast<const float4*>(&g_xw0[c2 * H1_DIM + s * 4]);
    red_add_v4(&g_h1[r1 * H1_DIM + s * 4], v1 * x1.x, v1 * x1.y, v1 * x1.z, v1 * x1.w);
    red_add_v4(&g_h1[r2 * H1_DIM + s * 4], v2 * x2.x, v2 * x2.y, v2 * x2.z, v2 * x2.w);
}

// ---------------- K3: ah1 = spmm(A, relu(h1))  (2 edges/thread) ------------
__global__ void k_spmm2(const int* __restrict__ rows, const int* __restrict__ cols,
                        const float* __restrict__ vals) {
    unsigned t = blockIdx.x * blockDim.x + threadIdx.x;    // < (E/2)*8
    unsigned e = t >> 3;
    unsigned s = t & 7;
    unsigned e2 = e + E_NNZ / 2;

    int   r1 = rows[e],  c1 = cols[e];
    float v1 = vals[e];
    int   r2 = rows[e2], c2 = cols[e2];
    float v2 = vals[e2];

    float4 x1 = *reinterpret_cast<const float4*>(&g_h1[c1 * H1_DIM + s * 4]);
    float4 x2 = *reinterpret_cast<const float4*>(&g_h1[c2 * H1_DIM + s * 4]);
    red_add_v4(&g_ah1[r1 * H1_DIM + s * 4],
               v1 * fmaxf(x1.x, 0.f), v1 * fmaxf(x1.y, 0.f),
               v1 * fmaxf(x1.z, 0.f), v1 * fmaxf(x1.w, 0.f));
    red_add_v4(&g_ah1[r2 * H1_DIM + s * 4],
               v2 * fmaxf(x2.x, 0.f), v2 * fmaxf(x2.y, 0.f),
               v2 * fmaxf(x2.z, 0.f), v2 * fmaxf(x2.w, 0.f));
}

// ---------------- K4: fused heads: t = ah1@[W1|W2|W3], softmax, reparam ----
// Valid because spmm(A, h1@Wk) == (spmm(A, h1))@Wk  (associativity).
// 512-thread blocks, 32 rows each, grid 256 (covers all 148 SMs).
__global__ void __launch_bounds__(512) k_fuse(
        const float* __restrict__ W1, const float* __restrict__ W2,
        const float* __restrict__ W3,
        const float* __restrict__ s1, const float* __restrict__ s2) {
    __shared__ float sW[32 * 48];
    __shared__ float srow[32 * 32];
    int tid = threadIdx.x;
    {
        int i = tid;          // 0..511 covers all 512 weight elems per matrix
        int k = i >> 4, j = i & 15;
        sW[k * 48 + j]      = W1[i];
        sW[k * 48 + 16 + j] = W2[i];
        sW[k * 48 + 32 + j] = W3[i];
    }
    int row0 = blockIdx.x * 32;
    if (tid < 256) {
        int r  = tid >> 3;
        int c4 = (tid & 7) * 4;
        *reinterpret_cast<float4*>(&srow[r * 32 + c4]) =
            *reinterpret_cast<const float4*>(&g_ah1[(size_t)(row0 + r) * 32 + c4]);
    }
    __syncthreads();

    int rr = tid >> 4;     // local row 0..31
    int l  = tid & 15;     // output col 0..15
    float a1 = 0.f, a2 = 0.f, a3 = 0.f;
#pragma unroll
    for (int k = 0; k < 32; k++) {
        float v = srow[rr * 32 + k];
        a1 = fmaf(v, sW[k * 48 + l],      a1);
        a2 = fmaf(v, sW[k * 48 + 16 + l], a2);
        a3 = fmaf(v, sW[k * 48 + 32 + l], a3);
    }

    float m2 = a2, m3 = a3;
#pragma unroll
    for (int d = 8; d; d >>= 1) {
        m2 = fmaxf(m2, __shfl_xor_sync(0xffffffffu, m2, d));
        m3 = fmaxf(m3, __shfl_xor_sync(0xffffffffu, m3, d));
    }
    float e2 = __expf(a2 - m2), e3 = __expf(a3 - m3);
    float q2 = e2, q3 = e3;
#pragma unroll
    for (int d = 8; d; d >>= 1) {
        q2 += __shfl_xor_sync(0xffffffffu, q2, d);
        q3 += __shfl_xor_sync(0xffffffffu, q3, d);
    }
    float p2 = __fdividef(e2, q2);          // z_log_en
    float p3 = __fdividef(e3, q3);          // z_log_he
    int row = row0 + rr;
    float z_enn = __expf(p2) + s1[row * 16 + l] * (0.1f * __expf(p3));
    g_z[row * 16 + l] = a1 + s2[row * 16 + l] * z_enn;
}

// ---------------- K6: out = z @ z^T, 128x32 tiles, occ=4, __stcs stores ----
#define ZPAD   18
#define SM_STR 132    // 33 vecs
#define ZZT_SMEM_BYTES (32 * SM_STR * 4)   // 16896; compute phase needs 11520

__global__ void __launch_bounds__(256, 4) k_zzt(float* __restrict__ out) {
    extern __shared__ float sm[];
    float* szi  = sm;                       // [128][ZPAD] (compute phase)
    float* szj  = sm + 128 * ZPAD;          // [32][ZPAD]
    float* sm_m = sm;                       // [32][SM_STR] (staging, overlaps)

    // block -> (lower-tri square tile l, quarter h)
    int bx = blockIdx.x;
    int l  = bx >> 2;
    int h  = bx & 3;
    float f = sqrtf(8.0f * (float)l + 1.0f);
    int bi = (int)((f - 1.0f) * 0.5f);
    while ((bi + 1) * (bi + 2) / 2 <= l) bi++;
    while (bi * (bi + 1) / 2 > l) bi--;
    int bj = l - bi * (bi + 1) / 2;

    int i0 = bi * 128;
    int j0 = bj * 128 + h * 32;
    int tid = threadIdx.x;

    // load z tiles: szi 128x16 (512 float4, 2/thread); szj 32x16 (128 float4)
#pragma unroll
    for (int q = 0; q < 2; q++) {
        int idx = q * 256 + tid;
        int r = idx >> 2;
        int c = (idx & 3) * 4;
        float4 vi = *reinterpret_cast<const float4*>(&g_z[(i0 + r) * 16 + c]);
        *reinterpret_cast<float2*>(&szi[r * ZPAD + c])     = make_float2(vi.x, vi.y);
        *reinterpret_cast<float2*>(&szi[r * ZPAD + c + 2]) = make_float2(vi.z, vi.w);
    }
    if (tid < 128) {
        int r = tid >> 2;
        int c = (tid & 3) * 4;
        float4 vj = *reinterpret_cast<const float4*>(&g_z[(j0 + r) * 16 + c]);
        *reinterpret_cast<float2*>(&szj[r * ZPAD + c])     = make_float2(vj.x, vj.y);
        *reinterpret_cast<float2*>(&szj[r * ZPAD + c + 2]) = make_float2(vj.z, vj.w);
    }
    __syncthreads();

    int ti = tid >> 4;    // 0..15 : rows ti+16r (r<8)
    int tj = tid & 15;    // 0..15 : cols tj+16c (c<2)

    unsigned long long acc[8][2];
#pragma unroll
    for (int r = 0; r < 8; r++)
#pragma unroll
        for (int c = 0; c < 2; c++) acc[r][c] = 0ull;

#pragma unroll
    for (int kp = 0; kp < 8; kp++) {
        unsigned long long a[8], b[2];
#pragma unroll
        for (int r = 0; r < 8; r++)
            a[r] = *reinterpret_cast<const unsigned long long*>(
                &szi[(ti + 16 * r) * ZPAD + 2 * kp]);
#pragma unroll
        for (int c = 0; c < 2; c++)
            b[c] = *reinterpret_cast<const unsigned long long*>(
                &szj[(tj + 16 * c) * ZPAD + 2 * kp]);
#pragma unroll
        for (int r = 0; r < 8; r++)
#pragma unroll
            for (int c = 0; c < 2; c++) fma_f32x2(acc[r][c], a[r], b[c]);
    }

    bool mirror = (bi != bj);

    // finalize; store direct tile straight from registers (streaming)
    float res[8][2];
#pragma unroll
    for (int r = 0; r < 8; r++)
#pragma unroll
        for (int c = 0; c < 2; c++) {
            unsigned long long u = acc[r][c];
            float lo = __int_as_float((int)(u & 0xffffffffull));
            float hi = __int_as_float((int)(u >> 32));
            res[r][c] = lo + hi;
            __stcs(&out[(size_t)(i0 + ti + 16 * r) * N_NODES + j0 + tj + 16 * c],
                   res[r][c]);
        }

    // mirror tile via smem transpose staging
    if (mirror) {
        __syncthreads();    // compute-phase smem reads done before overwrite
#pragma unroll
        for (int r = 0; r < 8; r++)
#pragma unroll
            for (int c = 0; c < 2; c++)
                sm_m[(tj + 16 * c) * SM_STR + ti + 16 * r] = res[r][c];
        __syncthreads();

        int lane = tid & 31;
        int w    = tid >> 5;   // 0..7, warp handles rows 4w..4w+3
#pragma unroll
        for (int m = 0; m < 4; m++) {
            int j = 4 * w + m;
            float4 v = *reinterpret_cast<const float4*>(&sm_m[j * SM_STR + 4 * lane]);
            __stcs(reinterpret_cast<float4*>(
                       &out[(size_t)(j0 + j) * N_NODES + i0 + 4 * lane]), v);
        }
    }
}

// ---------------- launcher ---------------------------------------------------
extern "C" void kernel_launch(void* const* d_in, const int* in_sizes, int n_in,
                              void* d_out, int out_size) {
    const float* features = (const float*)d_in[0];
    const int*   adj_rows = (const int*)  d_in[1];
    const int*   adj_cols = (const int*)  d_in[2];
    const float* adj_val  = (const float*)d_in[3];
    const float* W0       = (const float*)d_in[4];
    const float* W1       = (const float*)d_in[5];
    const float* W2       = (const float*)d_in[6];
    const float* W3       = (const float*)d_in[7];
    const float* sample_1 = (const float*)d_in[8];
    const float* sample_2 = (const float*)d_in[9];
    float* out = (float*)d_out;

    cudaFuncSetAttribute(k_zzt, cudaFuncAttributeMaxDynamicSharedMemorySize,
                         ZZT_SMEM_BYTES);

    k_xw0  <<<N_NODES / 32, 256>>>(features, W0);
    k_spmm1<<<E_NNZ * 4 / 256, 256>>>(adj_rows, adj_cols, adj_val);
    k_spmm2<<<E_NNZ * 4 / 256, 256>>>(adj_rows, adj_cols, adj_val);
    k_fuse <<<N_NODES / 32, 512>>>(W1, W2, W3, sample_1, sample_2);

    int ntiles = (N_NODES / 128) * (N_NODES / 128 + 1) / 2;   // 2080
    k_zzt<<<ntiles * 4, 256, ZZT_SMEM_BYTES>>>(out);
}